// round 2
// baseline (speedup 1.0000x reference)
#include <cuda_runtime.h>
#include <cuda_bf16.h>
#include <math.h>

#define R  3
#define Nn 20000
#define E  320000
#define F  256
#define H  8
#define O  64
#define D  512          // H*O

// ---------------- scratch (static device globals; no allocations) ----------------
__device__ float g_h[(size_t)R * Nn * D];        // projected features per relation
__device__ float g_z[(size_t)R * Nn * D];        // GAT output per relation (post relu6)
__device__ float g_el[R * Nn * H];
__device__ float g_er[R * Nn * H];
__device__ int   g_cnt[R * Nn];
__device__ int   g_rowptr[R * (Nn + 1)];
__device__ int   g_cursor[R * Nn];
__device__ int   g_eid[(size_t)R * E];
__device__ float g_attn[(size_t)R * E * H];
__device__ float g_t[(size_t)R * Nn * O];        // tanh(z@W1+b1)
__device__ float g_w[R * Nn];
__device__ float g_wmean[R];
__device__ float g_beta[R];

// ---------------- zero counts ----------------
__global__ void k_zero_cnt() {
    int t = blockIdx.x * blockDim.x + threadIdx.x;
    if (t < R * Nn) g_cnt[t] = 0;
}

// ---------------- fp32 tiled GEMM: C[M,Nd] = A[M,K] @ B[K,Nd] (batched over z) ----
#define BM 64
#define BN 64
#define BK 16
__global__ void k_gemm(const float* __restrict__ A0, const float* __restrict__ B0,
                       float* __restrict__ C0, const float* __restrict__ bias,
                       int M, int K, int Nd,
                       size_t sA, size_t sB, size_t sC, int mode) {
    const float* A = A0 + (size_t)blockIdx.z * sA;
    const float* B = B0 + (size_t)blockIdx.z * sB;
    float*       C = C0 + (size_t)blockIdx.z * sC;

    __shared__ float As[BK][BM];
    __shared__ float Bs[BK][BN];

    int tid = threadIdx.x;           // 256 threads
    int m0 = blockIdx.x * BM;
    int n0 = blockIdx.y * BN;
    int tx = tid & 15;               // 0..15 -> 4 cols each
    int ty = tid >> 4;               // 0..15 -> 4 rows each

    int la_m = tid >> 2;             // 0..63
    int la_k = (tid & 3) * 4;        // 0,4,8,12
    int lb_k = tid >> 4;             // 0..15
    int lb_n = (tid & 15) * 4;       // 0..60

    float acc[4][4] = {};

    for (int k0 = 0; k0 < K; k0 += BK) {
        float4 av = make_float4(0.f, 0.f, 0.f, 0.f);
        if (m0 + la_m < M)
            av = *(const float4*)(A + (size_t)(m0 + la_m) * K + k0 + la_k);
        As[la_k + 0][la_m] = av.x;
        As[la_k + 1][la_m] = av.y;
        As[la_k + 2][la_m] = av.z;
        As[la_k + 3][la_m] = av.w;

        float4 bv = *(const float4*)(B + (size_t)(k0 + lb_k) * Nd + n0 + lb_n);
        *(float4*)&Bs[lb_k][lb_n] = bv;
        __syncthreads();

#pragma unroll
        for (int kk = 0; kk < BK; kk++) {
            float4 ra = *(const float4*)&As[kk][ty * 4];
            float4 rb = *(const float4*)&Bs[kk][tx * 4];
            float a_[4] = {ra.x, ra.y, ra.z, ra.w};
            float b_[4] = {rb.x, rb.y, rb.z, rb.w};
#pragma unroll
            for (int i = 0; i < 4; i++)
#pragma unroll
                for (int j = 0; j < 4; j++)
                    acc[i][j] = fmaf(a_[i], b_[j], acc[i][j]);
        }
        __syncthreads();
    }

#pragma unroll
    for (int i = 0; i < 4; i++) {
        int row = m0 + ty * 4 + i;
        if (row >= M) continue;
        float4 o;
        o.x = acc[i][0]; o.y = acc[i][1]; o.z = acc[i][2]; o.w = acc[i][3];
        if (mode == 1) {
            int nc = n0 + tx * 4;
            o.x = tanhf(o.x + bias[nc + 0]);
            o.y = tanhf(o.y + bias[nc + 1]);
            o.z = tanhf(o.z + bias[nc + 2]);
            o.w = tanhf(o.w + bias[nc + 3]);
        }
        *(float4*)(C + (size_t)row * Nd + n0 + tx * 4) = o;
    }
}

// ---------------- el/er = einsum over O -------------------------------------------
__global__ void k_elr(const float* __restrict__ al, const float* __restrict__ ar) {
    int t = blockIdx.x * blockDim.x + threadIdx.x;
    if (t >= R * Nn * H) return;
    int h = t % H;
    int n = (t / H) % Nn;
    int r = t / (H * Nn);
    const float* hr  = g_h + ((size_t)(r * Nn + n)) * D + h * O;
    const float* alr = al + (r * H + h) * O;
    const float* arr = ar + (r * H + h) * O;
    float sl = 0.f, sr = 0.f;
#pragma unroll 8
    for (int o = 0; o < O; o++) {
        float v = hr[o];
        sl = fmaf(v, alr[o], sl);
        sr = fmaf(v, arr[o], sr);
    }
    g_el[t] = sl;
    g_er[t] = sr;
}

// ---------------- CSR build -------------------------------------------------------
__global__ void k_hist(const int* __restrict__ dstA) {
    int t = blockIdx.x * blockDim.x + threadIdx.x;
    if (t >= R * E) return;
    int r = t / E;
    atomicAdd(&g_cnt[r * Nn + dstA[t]], 1);
}

__global__ void k_scan() {   // one block (1024 thr) per relation; exclusive scan
    int r = blockIdx.x;
    __shared__ int sh[2048];
    __shared__ int carry;
    int t = threadIdx.x;
    if (t == 0) carry = 0;
    __syncthreads();
    const int* cnt = g_cnt + r * Nn;
    int* rp = g_rowptr + r * (Nn + 1);
    for (int base = 0; base < Nn; base += 1024) {
        int i = base + t;
        int v = (i < Nn) ? cnt[i] : 0;
        int pin = 0, pout = 1;
        sh[t] = v;
        __syncthreads();
        for (int off = 1; off < 1024; off <<= 1) {
            int x = sh[pin * 1024 + t];
            if (t >= off) x += sh[pin * 1024 + t - off];
            sh[pout * 1024 + t] = x;
            __syncthreads();
            pin ^= 1; pout ^= 1;
        }
        int incl = sh[pin * 1024 + t];
        if (i < Nn) rp[i] = carry + incl - v;   // exclusive
        __syncthreads();
        if (t == 1023) carry += incl;
        __syncthreads();
    }
    if (t == 0) rp[Nn] = carry;
}

__global__ void k_copy_cursor() {
    int t = blockIdx.x * blockDim.x + threadIdx.x;
    if (t >= R * Nn) return;
    int r = t / Nn, n = t % Nn;
    g_cursor[t] = g_rowptr[r * (Nn + 1) + n];
}

__global__ void k_scatter(const int* __restrict__ dstA) {
    int t = blockIdx.x * blockDim.x + threadIdx.x;
    if (t >= R * E) return;
    int r = t / E, e = t % E;
    int d = dstA[t];
    int p = atomicAdd(&g_cursor[r * Nn + d], 1);
    g_eid[(size_t)r * E + p] = e;
}

// ---------------- edge softmax: one thread per (r, dst, h) ------------------------
__global__ void k_softmax(const int* __restrict__ srcA) {
    int t = blockIdx.x * blockDim.x + threadIdx.x;
    if (t >= R * Nn * H) return;
    int h = t % H;
    int n = (t / H) % Nn;
    int r = t / (H * Nn);
    int s0 = g_rowptr[r * (Nn + 1) + n];
    int s1 = g_rowptr[r * (Nn + 1) + n + 1];
    if (s1 == s0) return;
    float erv = g_er[t];
    const int* src = srcA + (size_t)r * E;
    const int* eid = g_eid + (size_t)r * E;
    float* attn = g_attn + (size_t)r * E * H;

    float m = -3.4e38f;
    for (int p = s0; p < s1; p++) {
        int e = eid[p];
        float s = g_el[(src[e] + r * Nn) * H + h] + erv;
        s = (s > 0.f) ? s : 0.2f * s;
        attn[(size_t)p * H + h] = s;
        m = fmaxf(m, s);
    }
    float den = 0.f;
    for (int p = s0; p < s1; p++) {
        float ex = expf(attn[(size_t)p * H + h] - m);
        attn[(size_t)p * H + h] = ex;
        den += ex;
    }
    float inv = 1.f / den;
    for (int p = s0; p < s1; p++)
        attn[(size_t)p * H + h] *= inv;
}

// ---------------- aggregate: one 128-thread block per (r, dst) --------------------
__global__ void k_aggregate(const int* __restrict__ srcA, const float* __restrict__ bias) {
    int n = blockIdx.x;
    int r = blockIdx.y;
    int tid = threadIdx.x;       // 128
    int col = tid * 4;
    int h = tid >> 4;
    int s0 = g_rowptr[r * (Nn + 1) + n];
    int s1 = g_rowptr[r * (Nn + 1) + n + 1];
    const int* src = srcA + (size_t)r * E;
    const int* eid = g_eid + (size_t)r * E;
    const float* attn = g_attn + (size_t)r * E * H;
    const float* hb = g_h + (size_t)r * Nn * D;

    float a0 = 0.f, a1 = 0.f, a2 = 0.f, a3 = 0.f;
    for (int p = s0; p < s1; p++) {
        int e = eid[p];
        int sn = src[e];
        float a = attn[(size_t)p * H + h];
        float4 v = *(const float4*)(hb + (size_t)sn * D + col);
        a0 = fmaf(a, v.x, a0);
        a1 = fmaf(a, v.y, a1);
        a2 = fmaf(a, v.z, a2);
        a3 = fmaf(a, v.w, a3);
    }
    float4 bv = *(const float4*)(bias + r * D + col);
    float4 o;
    o.x = fminf(fmaxf(a0 + bv.x, 0.f), 6.f);
    o.y = fminf(fmaxf(a1 + bv.y, 0.f), 6.f);
    o.z = fminf(fmaxf(a2 + bv.z, 0.f), 6.f);
    o.w = fminf(fmaxf(a3 + bv.w, 0.f), 6.f);
    *(float4*)(g_z + ((size_t)(r * Nn + n)) * D + col) = o;
}

// ---------------- w = t @ W2 : one warp per (r, n) --------------------------------
__global__ void k_w2(const float* __restrict__ W2) {
    int gw = (blockIdx.x * blockDim.x + threadIdx.x) >> 5;
    if (gw >= R * Nn) return;
    int lane = threadIdx.x & 31;
    int r = gw / Nn, n = gw % Nn;
    const float* tp = g_t + (size_t)(r * Nn + n) * O;
    float s = tp[lane] * W2[lane] + tp[lane + 32] * W2[lane + 32];
#pragma unroll
    for (int off = 16; off > 0; off >>= 1)
        s += __shfl_xor_sync(0xFFFFFFFFu, s, off);
    if (lane == 0) g_w[gw] = s;
}

// ---------------- deterministic mean over nodes -----------------------------------
__global__ void k_wreduce() {
    int r = blockIdx.x;
    __shared__ float sh[1024];
    float s = 0.f;
    for (int i = threadIdx.x; i < Nn; i += 1024) s += g_w[r * Nn + i];
    sh[threadIdx.x] = s;
    __syncthreads();
    for (int off = 512; off > 0; off >>= 1) {
        if (threadIdx.x < off) sh[threadIdx.x] += sh[threadIdx.x + off];
        __syncthreads();
    }
    if (threadIdx.x == 0) g_wmean[r] = sh[0] / (float)Nn;
}

__global__ void k_beta() {
    if (threadIdx.x == 0) {
        float m = fmaxf(g_wmean[0], fmaxf(g_wmean[1], g_wmean[2]));
        float e0 = expf(g_wmean[0] - m);
        float e1 = expf(g_wmean[1] - m);
        float e2 = expf(g_wmean[2] - m);
        float inv = 1.f / (e0 + e1 + e2);
        g_beta[0] = e0 * inv;
        g_beta[1] = e1 * inv;
        g_beta[2] = e2 * inv;
    }
}

// ---------------- out = sum_r beta[r] * z[:, r, :] --------------------------------
__global__ void k_out(float* __restrict__ out) {
    int i = blockIdx.x * blockDim.x + threadIdx.x;
    if (i >= Nn * D / 4) return;
    float b0 = g_beta[0], b1 = g_beta[1], b2 = g_beta[2];
    const float4* z0 = (const float4*)g_z;
    const float4* z1 = (const float4*)(g_z + (size_t)Nn * D);
    const float4* z2 = (const float4*)(g_z + (size_t)2 * Nn * D);
    float4 v0 = z0[i], v1 = z1[i], v2 = z2[i];
    float4 o;
    o.x = b0 * v0.x + b1 * v1.x + b2 * v2.x;
    o.y = b0 * v0.y + b1 * v1.y + b2 * v2.y;
    o.z = b0 * v0.z + b1 * v1.z + b2 * v2.z;
    o.w = b0 * v0.w + b1 * v1.w + b2 * v2.w;
    ((float4*)out)[i] = o;
}

// ---------------- host ------------------------------------------------------------
extern "C" void kernel_launch(void* const* d_in, const int* in_sizes, int n_in,
                              void* d_out, int out_size) {
    const float* feats = (const float*)d_in[0];
    const int*   src   = (const int*)d_in[1];
    const int*   dst   = (const int*)d_in[2];
    const float* W     = (const float*)d_in[3];
    const float* al    = (const float*)d_in[4];
    const float* ar    = (const float*)d_in[5];
    const float* bias  = (const float*)d_in[6];
    const float* W1    = (const float*)d_in[7];
    const float* b1    = (const float*)d_in[8];
    const float* W2    = (const float*)d_in[9];
    float* out = (float*)d_out;

    float *hptr, *zptr, *tptr;
    cudaGetSymbolAddress((void**)&hptr, g_h);
    cudaGetSymbolAddress((void**)&zptr, g_z);
    cudaGetSymbolAddress((void**)&tptr, g_t);

    // GEMM1: h[r] = feats[r] @ W[r]
    k_gemm<<<dim3((Nn + BM - 1) / BM, D / BN, R), 256>>>(
        feats, W, hptr, nullptr, Nn, F, D,
        (size_t)Nn * F, (size_t)F * D, (size_t)Nn * D, 0);

    k_elr<<<(R * Nn * H + 255) / 256, 256>>>(al, ar);

    // CSR build
    k_zero_cnt<<<(R * Nn + 255) / 256, 256>>>();
    k_hist<<<(R * E + 255) / 256, 256>>>(dst);
    k_scan<<<R, 1024>>>();
    k_copy_cursor<<<(R * Nn + 255) / 256, 256>>>();
    k_scatter<<<(R * E + 255) / 256, 256>>>(dst);

    // edge softmax + aggregate
    k_softmax<<<(R * Nn * H + 255) / 256, 256>>>(src);
    k_aggregate<<<dim3(Nn, R), 128>>>(src, bias);

    // path attention
    k_gemm<<<dim3((Nn + BM - 1) / BM, O / BN, R), 256>>>(
        zptr, W1, tptr, b1, Nn, D, O,
        (size_t)Nn * D, 0, (size_t)Nn * O, 1);
    k_w2<<<(R * Nn * 32 + 255) / 256, 256>>>(W2);
    k_wreduce<<<R, 1024>>>();
    k_beta<<<1, 32>>>();
    k_out<<<(Nn * D / 4 + 255) / 256, 256>>>(out);
}

// round 3
// speedup vs baseline: 1.3293x; 1.3293x over previous
#include <cuda_runtime.h>
#include <cuda_bf16.h>
#include <math.h>

#define R  3
#define Nn 20000
#define E  320000
#define F  256
#define H  8
#define O  64
#define D  512          // H*O

// ---------------- scratch (static device globals; no allocations) ----------------
__device__ float g_h[(size_t)R * Nn * D];        // projected features per relation
__device__ float g_z[(size_t)R * Nn * D];        // GAT output per relation (post relu6)
__device__ float g_el[R * Nn * H];
__device__ float g_er[R * Nn * H];
__device__ int   g_cnt[R * Nn];
__device__ int   g_rowptr[R * (Nn + 1)];
__device__ int   g_cursor[R * Nn];
__device__ int   g_eid[(size_t)R * E];
__device__ float g_attn[(size_t)R * E * H];
__device__ float g_t[(size_t)R * Nn * O];        // tanh(z@W1+b1)
__device__ float g_w[R * Nn];
__device__ float g_wmean[R];
__device__ float g_beta[R];

// ---------------- zero counts ----------------
__global__ void k_zero_cnt() {
    int t = blockIdx.x * blockDim.x + threadIdx.x;
    if (t < R * Nn) g_cnt[t] = 0;
}

// ================= TF32 tensor-core GEMM =========================================
// C[M,Nd] = A[M,K] @ B[K,Nd], batched over blockIdx.z.
// mode==1: C = tanh(C + bias[col])
#define GBM 128
#define GBN 64
#define GBK 32
#define ASTR (GBM + 4)     // 132
#define BSTR (GBN + 4)     // 68
#define ASZ (GBK * ASTR)
#define BSZ (GBK * BSTR)
#define GSMEM (2 * (ASZ + BSZ) * sizeof(float))

__device__ __forceinline__ float tf32r(float x) {
    float y;
    asm("cvt.rna.tf32.f32 %0, %1;" : "=f"(y) : "f"(x));
    return y;
}

__global__ void __launch_bounds__(256, 2) k_gemm_tc(
    const float* __restrict__ A0, const float* __restrict__ B0,
    float* __restrict__ C0, const float* __restrict__ bias,
    int M, int K, int Nd,
    size_t sA, size_t sB, size_t sC, int mode)
{
    extern __shared__ float dsm[];
    float* Asm[2] = {dsm, dsm + ASZ};
    float* Bsm[2] = {dsm + 2 * ASZ, dsm + 2 * ASZ + BSZ};

    const float* A = A0 + (size_t)blockIdx.z * sA;
    const float* B = B0 + (size_t)blockIdx.z * sB;
    float*       C = C0 + (size_t)blockIdx.z * sC;

    const int tid  = threadIdx.x;
    const int lane = tid & 31, wid = tid >> 5;
    const int gid  = lane >> 2, tig = lane & 3;
    const int wm   = wid >> 1, wn = wid & 1;          // 4 x 2 warp grid
    const int m0   = blockIdx.x * GBM, n0 = blockIdx.y * GBN;

    // gmem staging indices: A -> 4 float4 / thread, B -> 2 float4 / thread
    int aRow[4], aC4[4];
#pragma unroll
    for (int i = 0; i < 4; i++) {
        int idx = tid + i * 256;
        aRow[i] = idx >> 3;
        aC4[i]  = (idx & 7) * 4;
    }
    int bRow[2], bC4[2];
#pragma unroll
    for (int i = 0; i < 2; i++) {
        int idx = tid + i * 256;
        bRow[i] = idx >> 4;
        bC4[i]  = (idx & 15) * 4;
    }

    float c[2][4][4] = {};
    float4 ar[4], br[2];

    // ---- prologue: load + convert + store tile 0 ----
#pragma unroll
    for (int i = 0; i < 4; i++) {
        int gr = m0 + aRow[i];
        ar[i] = (gr < M) ? *(const float4*)(A + (size_t)gr * K + aC4[i])
                         : make_float4(0.f, 0.f, 0.f, 0.f);
    }
#pragma unroll
    for (int i = 0; i < 2; i++)
        br[i] = *(const float4*)(B + (size_t)bRow[i] * Nd + n0 + bC4[i]);

#pragma unroll
    for (int i = 0; i < 4; i++) {
        float* p = Asm[0];
        p[(aC4[i] + 0) * ASTR + aRow[i]] = tf32r(ar[i].x);
        p[(aC4[i] + 1) * ASTR + aRow[i]] = tf32r(ar[i].y);
        p[(aC4[i] + 2) * ASTR + aRow[i]] = tf32r(ar[i].z);
        p[(aC4[i] + 3) * ASTR + aRow[i]] = tf32r(ar[i].w);
    }
#pragma unroll
    for (int i = 0; i < 2; i++) {
        float4 v;
        v.x = tf32r(br[i].x); v.y = tf32r(br[i].y);
        v.z = tf32r(br[i].z); v.w = tf32r(br[i].w);
        *(float4*)(Bsm[0] + bRow[i] * BSTR + bC4[i]) = v;
    }
    __syncthreads();

    const int T = K / GBK;
    for (int it = 0; it < T; it++) {
        const int cur = it & 1;
        const int k0n = (it + 1) * GBK;

        if (it + 1 < T) {
#pragma unroll
            for (int i = 0; i < 4; i++) {
                int gr = m0 + aRow[i];
                ar[i] = (gr < M) ? *(const float4*)(A + (size_t)gr * K + k0n + aC4[i])
                                 : make_float4(0.f, 0.f, 0.f, 0.f);
            }
#pragma unroll
            for (int i = 0; i < 2; i++)
                br[i] = *(const float4*)(B + (size_t)(k0n + bRow[i]) * Nd + n0 + bC4[i]);
        }

        // ---- compute on buffer 'cur' ----
        const float* As = Asm[cur];
        const float* Bs = Bsm[cur];
#pragma unroll
        for (int kk = 0; kk < GBK; kk += 8) {
            unsigned a[2][4], b[4][2];
#pragma unroll
            for (int i = 0; i < 2; i++) {
                int mr = wm * 32 + i * 16 + gid;
                a[i][0] = __float_as_uint(As[(kk + tig) * ASTR + mr]);
                a[i][1] = __float_as_uint(As[(kk + tig) * ASTR + mr + 8]);
                a[i][2] = __float_as_uint(As[(kk + tig + 4) * ASTR + mr]);
                a[i][3] = __float_as_uint(As[(kk + tig + 4) * ASTR + mr + 8]);
            }
#pragma unroll
            for (int j = 0; j < 4; j++) {
                int nc = wn * 32 + j * 8 + gid;
                b[j][0] = __float_as_uint(Bs[(kk + tig) * BSTR + nc]);
                b[j][1] = __float_as_uint(Bs[(kk + tig + 4) * BSTR + nc]);
            }
#pragma unroll
            for (int i = 0; i < 2; i++)
#pragma unroll
                for (int j = 0; j < 4; j++)
                    asm volatile(
                        "mma.sync.aligned.m16n8k8.row.col.f32.tf32.tf32.f32 "
                        "{%0,%1,%2,%3}, {%4,%5,%6,%7}, {%8,%9}, {%0,%1,%2,%3};"
                        : "+f"(c[i][j][0]), "+f"(c[i][j][1]),
                          "+f"(c[i][j][2]), "+f"(c[i][j][3])
                        : "r"(a[i][0]), "r"(a[i][1]), "r"(a[i][2]), "r"(a[i][3]),
                          "r"(b[j][0]), "r"(b[j][1]));
        }

        if (it + 1 < T) {
            float* p = Asm[cur ^ 1];
#pragma unroll
            for (int i = 0; i < 4; i++) {
                p[(aC4[i] + 0) * ASTR + aRow[i]] = tf32r(ar[i].x);
                p[(aC4[i] + 1) * ASTR + aRow[i]] = tf32r(ar[i].y);
                p[(aC4[i] + 2) * ASTR + aRow[i]] = tf32r(ar[i].z);
                p[(aC4[i] + 3) * ASTR + aRow[i]] = tf32r(ar[i].w);
            }
            float* q = Bsm[cur ^ 1];
#pragma unroll
            for (int i = 0; i < 2; i++) {
                float4 v;
                v.x = tf32r(br[i].x); v.y = tf32r(br[i].y);
                v.z = tf32r(br[i].z); v.w = tf32r(br[i].w);
                *(float4*)(q + bRow[i] * BSTR + bC4[i]) = v;
            }
        }
        __syncthreads();
    }

    // ---- epilogue ----
#pragma unroll
    for (int i = 0; i < 2; i++) {
        int row = m0 + wm * 32 + i * 16 + gid;
#pragma unroll
        for (int j = 0; j < 4; j++) {
            int col = n0 + wn * 32 + j * 8 + 2 * tig;
            float2 v0 = make_float2(c[i][j][0], c[i][j][1]);
            float2 v1 = make_float2(c[i][j][2], c[i][j][3]);
            if (mode == 1) {
                float b0 = bias[col], b1v = bias[col + 1];
                v0.x = tanhf(v0.x + b0); v0.y = tanhf(v0.y + b1v);
                v1.x = tanhf(v1.x + b0); v1.y = tanhf(v1.y + b1v);
            }
            if (row < M)     *(float2*)(C + (size_t)row * Nd + col) = v0;
            if (row + 8 < M) *(float2*)(C + (size_t)(row + 8) * Nd + col) = v1;
        }
    }
}

// ---------------- el/er = einsum over O -------------------------------------------
__global__ void k_elr(const float* __restrict__ al, const float* __restrict__ ar) {
    int t = blockIdx.x * blockDim.x + threadIdx.x;
    if (t >= R * Nn * H) return;
    int h = t % H;
    int n = (t / H) % Nn;
    int r = t / (H * Nn);
    const float* hr  = g_h + ((size_t)(r * Nn + n)) * D + h * O;
    const float* alr = al + (r * H + h) * O;
    const float* arr = ar + (r * H + h) * O;
    float sl = 0.f, sr = 0.f;
#pragma unroll 8
    for (int o = 0; o < O; o++) {
        float v = hr[o];
        sl = fmaf(v, alr[o], sl);
        sr = fmaf(v, arr[o], sr);
    }
    g_el[t] = sl;
    g_er[t] = sr;
}

// ---------------- CSR build -------------------------------------------------------
__global__ void k_hist(const int* __restrict__ dstA) {
    int t = blockIdx.x * blockDim.x + threadIdx.x;
    if (t >= R * E) return;
    int r = t / E;
    atomicAdd(&g_cnt[r * Nn + dstA[t]], 1);
}

__global__ void k_scan() {   // one block (1024 thr) per relation; exclusive scan
    int r = blockIdx.x;
    __shared__ int sh[2048];
    __shared__ int carry;
    int t = threadIdx.x;
    if (t == 0) carry = 0;
    __syncthreads();
    const int* cnt = g_cnt + r * Nn;
    int* rp = g_rowptr + r * (Nn + 1);
    for (int base = 0; base < Nn; base += 1024) {
        int i = base + t;
        int v = (i < Nn) ? cnt[i] : 0;
        int pin = 0, pout = 1;
        sh[t] = v;
        __syncthreads();
        for (int off = 1; off < 1024; off <<= 1) {
            int x = sh[pin * 1024 + t];
            if (t >= off) x += sh[pin * 1024 + t - off];
            sh[pout * 1024 + t] = x;
            __syncthreads();
            pin ^= 1; pout ^= 1;
        }
        int incl = sh[pin * 1024 + t];
        if (i < Nn) rp[i] = carry + incl - v;   // exclusive
        __syncthreads();
        if (t == 1023) carry += incl;
        __syncthreads();
    }
    if (t == 0) rp[Nn] = carry;
}

__global__ void k_copy_cursor() {
    int t = blockIdx.x * blockDim.x + threadIdx.x;
    if (t >= R * Nn) return;
    int r = t / Nn, n = t % Nn;
    g_cursor[t] = g_rowptr[r * (Nn + 1) + n];
}

__global__ void k_scatter(const int* __restrict__ dstA) {
    int t = blockIdx.x * blockDim.x + threadIdx.x;
    if (t >= R * E) return;
    int r = t / E, e = t % E;
    int d = dstA[t];
    int p = atomicAdd(&g_cursor[r * Nn + d], 1);
    g_eid[(size_t)r * E + p] = e;
}

// ---------------- edge softmax: one thread per (r, dst, h) ------------------------
__global__ void k_softmax(const int* __restrict__ srcA) {
    int t = blockIdx.x * blockDim.x + threadIdx.x;
    if (t >= R * Nn * H) return;
    int h = t % H;
    int n = (t / H) % Nn;
    int r = t / (H * Nn);
    int s0 = g_rowptr[r * (Nn + 1) + n];
    int s1 = g_rowptr[r * (Nn + 1) + n + 1];
    if (s1 == s0) return;
    float erv = g_er[t];
    const int* src = srcA + (size_t)r * E;
    const int* eid = g_eid + (size_t)r * E;
    float* attn = g_attn + (size_t)r * E * H;

    float m = -3.4e38f;
    for (int p = s0; p < s1; p++) {
        int e = eid[p];
        float s = g_el[(src[e] + r * Nn) * H + h] + erv;
        s = (s > 0.f) ? s : 0.2f * s;
        attn[(size_t)p * H + h] = s;
        m = fmaxf(m, s);
    }
    float den = 0.f;
    for (int p = s0; p < s1; p++) {
        float ex = expf(attn[(size_t)p * H + h] - m);
        attn[(size_t)p * H + h] = ex;
        den += ex;
    }
    float inv = 1.f / den;
    for (int p = s0; p < s1; p++)
        attn[(size_t)p * H + h] *= inv;
}

// ---------------- aggregate: one 128-thread block per (r, dst) --------------------
__global__ void k_aggregate(const int* __restrict__ srcA, const float* __restrict__ bias) {
    int n = blockIdx.x;
    int r = blockIdx.y;
    int tid = threadIdx.x;       // 128
    int col = tid * 4;
    int h = tid >> 4;
    int s0 = g_rowptr[r * (Nn + 1) + n];
    int s1 = g_rowptr[r * (Nn + 1) + n + 1];
    const int* src = srcA + (size_t)r * E;
    const int* eid = g_eid + (size_t)r * E;
    const float* attn = g_attn + (size_t)r * E * H;
    const float* hb = g_h + (size_t)r * Nn * D;

    float a0 = 0.f, a1 = 0.f, a2 = 0.f, a3 = 0.f;
    for (int p = s0; p < s1; p++) {
        int e = eid[p];
        int sn = src[e];
        float a = attn[(size_t)p * H + h];
        float4 v = *(const float4*)(hb + (size_t)sn * D + col);
        a0 = fmaf(a, v.x, a0);
        a1 = fmaf(a, v.y, a1);
        a2 = fmaf(a, v.z, a2);
        a3 = fmaf(a, v.w, a3);
    }
    float4 bv = *(const float4*)(bias + r * D + col);
    float4 o;
    o.x = fminf(fmaxf(a0 + bv.x, 0.f), 6.f);
    o.y = fminf(fmaxf(a1 + bv.y, 0.f), 6.f);
    o.z = fminf(fmaxf(a2 + bv.z, 0.f), 6.f);
    o.w = fminf(fmaxf(a3 + bv.w, 0.f), 6.f);
    *(float4*)(g_z + ((size_t)(r * Nn + n)) * D + col) = o;
}

// ---------------- w = t @ W2 : one warp per (r, n) --------------------------------
__global__ void k_w2(const float* __restrict__ W2) {
    int gw = (blockIdx.x * blockDim.x + threadIdx.x) >> 5;
    if (gw >= R * Nn) return;
    int lane = threadIdx.x & 31;
    int r = gw / Nn, n = gw % Nn;
    const float* tp = g_t + (size_t)(r * Nn + n) * O;
    float s = tp[lane] * W2[lane] + tp[lane + 32] * W2[lane + 32];
#pragma unroll
    for (int off = 16; off > 0; off >>= 1)
        s += __shfl_xor_sync(0xFFFFFFFFu, s, off);
    if (lane == 0) g_w[gw] = s;
}

// ---------------- deterministic mean over nodes -----------------------------------
__global__ void k_wreduce() {
    int r = blockIdx.x;
    __shared__ float sh[1024];
    float s = 0.f;
    for (int i = threadIdx.x; i < Nn; i += 1024) s += g_w[r * Nn + i];
    sh[threadIdx.x] = s;
    __syncthreads();
    for (int off = 512; off > 0; off >>= 1) {
        if (threadIdx.x < off) sh[threadIdx.x] += sh[threadIdx.x + off];
        __syncthreads();
    }
    if (threadIdx.x == 0) g_wmean[r] = sh[0] / (float)Nn;
}

__global__ void k_beta() {
    if (threadIdx.x == 0) {
        float m = fmaxf(g_wmean[0], fmaxf(g_wmean[1], g_wmean[2]));
        float e0 = expf(g_wmean[0] - m);
        float e1 = expf(g_wmean[1] - m);
        float e2 = expf(g_wmean[2] - m);
        float inv = 1.f / (e0 + e1 + e2);
        g_beta[0] = e0 * inv;
        g_beta[1] = e1 * inv;
        g_beta[2] = e2 * inv;
    }
}

// ---------------- out = sum_r beta[r] * z[:, r, :] --------------------------------
__global__ void k_out(float* __restrict__ out) {
    int i = blockIdx.x * blockDim.x + threadIdx.x;
    if (i >= Nn * D / 4) return;
    float b0 = g_beta[0], b1 = g_beta[1], b2 = g_beta[2];
    const float4* z0 = (const float4*)g_z;
    const float4* z1 = (const float4*)(g_z + (size_t)Nn * D);
    const float4* z2 = (const float4*)(g_z + (size_t)2 * Nn * D);
    float4 v0 = z0[i], v1 = z1[i], v2 = z2[i];
    float4 o;
    o.x = b0 * v0.x + b1 * v1.x + b2 * v2.x;
    o.y = b0 * v0.y + b1 * v1.y + b2 * v2.y;
    o.z = b0 * v0.z + b1 * v1.z + b2 * v2.z;
    o.w = b0 * v0.w + b1 * v1.w + b2 * v2.w;
    ((float4*)out)[i] = o;
}

// ---------------- host ------------------------------------------------------------
extern "C" void kernel_launch(void* const* d_in, const int* in_sizes, int n_in,
                              void* d_out, int out_size) {
    const float* feats = (const float*)d_in[0];
    const int*   src   = (const int*)d_in[1];
    const int*   dst   = (const int*)d_in[2];
    const float* W     = (const float*)d_in[3];
    const float* al    = (const float*)d_in[4];
    const float* ar    = (const float*)d_in[5];
    const float* bias  = (const float*)d_in[6];
    const float* W1    = (const float*)d_in[7];
    const float* b1    = (const float*)d_in[8];
    const float* W2    = (const float*)d_in[9];
    float* out = (float*)d_out;

    float *hptr, *zptr, *tptr;
    cudaGetSymbolAddress((void**)&hptr, g_h);
    cudaGetSymbolAddress((void**)&zptr, g_z);
    cudaGetSymbolAddress((void**)&tptr, g_t);

    cudaFuncSetAttribute(k_gemm_tc, cudaFuncAttributeMaxDynamicSharedMemorySize,
                         (int)GSMEM);

    // GEMM1: h[r] = feats[r] @ W[r]   (TF32 tensor core)
    k_gemm_tc<<<dim3((Nn + GBM - 1) / GBM, D / GBN, R), 256, GSMEM>>>(
        feats, W, hptr, nullptr, Nn, F, D,
        (size_t)Nn * F, (size_t)F * D, (size_t)Nn * D, 0);

    k_elr<<<(R * Nn * H + 255) / 256, 256>>>(al, ar);

    // CSR build
    k_zero_cnt<<<(R * Nn + 255) / 256, 256>>>();
    k_hist<<<(R * E + 255) / 256, 256>>>(dst);
    k_scan<<<R, 1024>>>();
    k_copy_cursor<<<(R * Nn + 255) / 256, 256>>>();
    k_scatter<<<(R * E + 255) / 256, 256>>>(dst);

    // edge softmax + aggregate
    k_softmax<<<(R * Nn * H + 255) / 256, 256>>>(src);
    k_aggregate<<<dim3(Nn, R), 128>>>(src, bias);

    // path attention: t = tanh(z @ W1 + b1)   (TF32 tensor core)
    k_gemm_tc<<<dim3((Nn + GBM - 1) / GBM, O / GBN, R), 256, GSMEM>>>(
        zptr, W1, tptr, b1, Nn, D, O,
        (size_t)Nn * D, 0, (size_t)Nn * O, 1);
    k_w2<<<(R * Nn * 32 + 255) / 256, 256>>>(W2);
    k_wreduce<<<R, 1024>>>();
    k_beta<<<1, 32>>>();
    k_out<<<(Nn * D / 4 + 255) / 256, 256>>>(out);
}

// round 4
// speedup vs baseline: 1.9315x; 1.4530x over previous
#include <cuda_runtime.h>
#include <cuda_bf16.h>
#include <math.h>

#define R  3
#define Nn 20000
#define E  320000
#define F  256
#define H  8
#define O  64
#define D  512          // H*O

// ---------------- scratch (static device globals; no allocations) ----------------
__device__ float g_h[(size_t)R * Nn * D];        // projected features per relation
__device__ float g_z[(size_t)R * Nn * D];        // GAT output per relation (post relu6)
__device__ float g_el[R * Nn * H];
__device__ float g_er[R * Nn * H];
__device__ int   g_cnt[R * Nn];
__device__ int   g_rowptr[R * (Nn + 1)];
__device__ int   g_cursor[R * Nn];
__device__ int   g_eid[(size_t)R * E];
__device__ float g_attn[(size_t)R * E * H];
__device__ float g_w[R * Nn];
__device__ float g_wmean[R];
__device__ float g_beta[R];

// ---------------- zero scratch accumulators ----------------
__global__ void k_zero() {
    int t = blockIdx.x * blockDim.x + threadIdx.x;
    if (t < R * Nn) { g_cnt[t] = 0; g_w[t] = 0.f; }
    if (t < R * Nn * H) { g_el[t] = 0.f; g_er[t] = 0.f; }
}

// ================= TF32 tensor-core GEMM (fused epilogues) ========================
// C[M,Nd] = A[M,K] @ B[K,Nd], batched over blockIdx.z.
// mode 0: store C=h, and accumulate el/er = h . al/ar per (row, head=blockIdx.y)
// mode 1: no C store; w[row] += sum_col tanh(C+bias[col]) * W2[col]
#define GBM 128
#define GBN 64
#define GBK 32
#define AST 36                      // A row stride (floats): conflict-free frag loads
#define BST 72                      // B k-row stride (floats): conflict-free
#define ASZ (GBM * AST)             // 4608
#define BSZ (GBK * BST)             // 2304
#define GSMEM (2 * (ASZ + BSZ) * sizeof(float))   // 55296 B

__device__ __forceinline__ float tf32r(float x) {
    float y;
    asm("cvt.rna.tf32.f32 %0, %1;" : "=f"(y) : "f"(x));
    return y;
}
__device__ __forceinline__ float4 cvt4(float4 v) {
    return make_float4(tf32r(v.x), tf32r(v.y), tf32r(v.z), tf32r(v.w));
}

__global__ void __launch_bounds__(128, 3) k_gemm_tc(
    const float* __restrict__ A0, const float* __restrict__ B0,
    float* __restrict__ C0,
    const float* __restrict__ alp, const float* __restrict__ arp,   // mode 0
    const float* __restrict__ bias, const float* __restrict__ W2p,  // mode 1
    int M, int K, int Nd,
    size_t sA, size_t sB, size_t sC, int mode)
{
    extern __shared__ float sm[];
    float* Asb[2] = {sm, sm + ASZ};
    float* Bsb[2] = {sm + 2 * ASZ, sm + 2 * ASZ + BSZ};

    const int bz = blockIdx.z;
    const float* A = A0 + (size_t)bz * sA;
    const float* B = B0 + (size_t)bz * sB;
    float*       C = C0 + (size_t)bz * sC;

    const int tid  = threadIdx.x;                 // 128
    const int lane = tid & 31, wid = tid >> 5;    // 4 warps
    const int gid  = lane >> 2, tig = lane & 3;
    const int wm   = wid >> 1, wn = wid & 1;      // 2x2 warp grid, warp tile 64x32
    const int m0   = blockIdx.x * GBM, n0 = blockIdx.y * GBN;

    // staging: A 8 float4/thread, B 4 float4/thread
    int aRow[8], aC[8];
#pragma unroll
    for (int i = 0; i < 8; i++) {
        int idx = tid + i * 128;
        aRow[i] = idx >> 3;            // 0..127
        aC[i]   = (idx & 7) * 4;       // 0..28
    }
    int bRow[4], bC[4];
#pragma unroll
    for (int i = 0; i < 4; i++) {
        int idx = tid + i * 128;
        bRow[i] = idx >> 4;            // 0..31
        bC[i]   = (idx & 15) * 4;      // 0..60
    }

    float c[4][4][4] = {};
    float4 sa[8], sb[4];

    // prologue: tile 0
#pragma unroll
    for (int i = 0; i < 8; i++) {
        int gr = m0 + aRow[i];
        sa[i] = (gr < M) ? *(const float4*)(A + (size_t)gr * K + aC[i])
                         : make_float4(0.f, 0.f, 0.f, 0.f);
    }
#pragma unroll
    for (int i = 0; i < 4; i++)
        sb[i] = *(const float4*)(B + (size_t)bRow[i] * Nd + n0 + bC[i]);
#pragma unroll
    for (int i = 0; i < 8; i++)
        *(float4*)(Asb[0] + aRow[i] * AST + aC[i]) = cvt4(sa[i]);
#pragma unroll
    for (int i = 0; i < 4; i++)
        *(float4*)(Bsb[0] + bRow[i] * BST + bC[i]) = cvt4(sb[i]);
    __syncthreads();

    const int T = K / GBK;
    for (int it = 0; it < T; it++) {
        const int cur = it & 1;
        if (it + 1 < T) {
            const int k0n = (it + 1) * GBK;
#pragma unroll
            for (int i = 0; i < 8; i++) {
                int gr = m0 + aRow[i];
                sa[i] = (gr < M) ? *(const float4*)(A + (size_t)gr * K + k0n + aC[i])
                                 : make_float4(0.f, 0.f, 0.f, 0.f);
            }
#pragma unroll
            for (int i = 0; i < 4; i++)
                sb[i] = *(const float4*)(B + (size_t)(k0n + bRow[i]) * Nd + n0 + bC[i]);
        }

        const float* As = Asb[cur];
        const float* Bs = Bsb[cur];
#pragma unroll
        for (int kg = 0; kg < 4; kg++) {
            unsigned a[4][4], b[4][2];
#pragma unroll
            for (int mt = 0; mt < 4; mt++) {
                int rb = (wm * 64 + mt * 16 + gid) * AST + kg * 8 + tig;
                a[mt][0] = __float_as_uint(As[rb]);
                a[mt][1] = __float_as_uint(As[rb + 8 * AST]);
                a[mt][2] = __float_as_uint(As[rb + 4]);
                a[mt][3] = __float_as_uint(As[rb + 8 * AST + 4]);
            }
#pragma unroll
            for (int nt = 0; nt < 4; nt++) {
                int cb = (kg * 8 + tig) * BST + wn * 32 + nt * 8 + gid;
                b[nt][0] = __float_as_uint(Bs[cb]);
                b[nt][1] = __float_as_uint(Bs[cb + 4 * BST]);
            }
#pragma unroll
            for (int mt = 0; mt < 4; mt++)
#pragma unroll
                for (int nt = 0; nt < 4; nt++)
                    asm volatile(
                        "mma.sync.aligned.m16n8k8.row.col.f32.tf32.tf32.f32 "
                        "{%0,%1,%2,%3}, {%4,%5,%6,%7}, {%8,%9}, {%0,%1,%2,%3};"
                        : "+f"(c[mt][nt][0]), "+f"(c[mt][nt][1]),
                          "+f"(c[mt][nt][2]), "+f"(c[mt][nt][3])
                        : "r"(a[mt][0]), "r"(a[mt][1]), "r"(a[mt][2]), "r"(a[mt][3]),
                          "r"(b[nt][0]), "r"(b[nt][1]));
        }

        if (it + 1 < T) {
            float* Aw = Asb[cur ^ 1];
            float* Bw = Bsb[cur ^ 1];
#pragma unroll
            for (int i = 0; i < 8; i++)
                *(float4*)(Aw + aRow[i] * AST + aC[i]) = cvt4(sa[i]);
#pragma unroll
            for (int i = 0; i < 4; i++)
                *(float4*)(Bw + bRow[i] * BST + bC[i]) = cvt4(sb[i]);
        }
        __syncthreads();
    }

    // ---- epilogues (smem buffers free after last sync) ----
    if (mode == 0) {
        // stage al/ar slice for this head (cols n0..n0+63)
        if (tid < 64) {
            sm[tid]      = alp[bz * D + n0 + tid];
            sm[64 + tid] = arp[bz * D + n0 + tid];
        }
        __syncthreads();
        const int hidx = blockIdx.y;
#pragma unroll
        for (int mt = 0; mt < 4; mt++) {
            int row = m0 + wm * 64 + mt * 16 + gid;
            float el0 = 0.f, er0 = 0.f, el1 = 0.f, er1 = 0.f;
#pragma unroll
            for (int nt = 0; nt < 4; nt++) {
                int o = wn * 32 + nt * 8 + 2 * tig;
                float al0 = sm[o], al1 = sm[o + 1];
                float ar0 = sm[64 + o], ar1 = sm[64 + o + 1];
                float v0 = c[mt][nt][0], v1 = c[mt][nt][1];
                float v2 = c[mt][nt][2], v3 = c[mt][nt][3];
                el0 = fmaf(v0, al0, fmaf(v1, al1, el0));
                er0 = fmaf(v0, ar0, fmaf(v1, ar1, er0));
                el1 = fmaf(v2, al0, fmaf(v3, al1, el1));
                er1 = fmaf(v2, ar0, fmaf(v3, ar1, er1));
                if (row < M)
                    *(float2*)(C + (size_t)row * Nd + n0 + o) = make_float2(v0, v1);
                if (row + 8 < M)
                    *(float2*)(C + (size_t)(row + 8) * Nd + n0 + o) = make_float2(v2, v3);
            }
#pragma unroll
            for (int off = 1; off <= 2; off <<= 1) {
                el0 += __shfl_xor_sync(0xFFFFFFFFu, el0, off);
                er0 += __shfl_xor_sync(0xFFFFFFFFu, er0, off);
                el1 += __shfl_xor_sync(0xFFFFFFFFu, el1, off);
                er1 += __shfl_xor_sync(0xFFFFFFFFu, er1, off);
            }
            if (tig == 0) {
                if (row < M) {
                    atomicAdd(&g_el[(bz * Nn + row) * H + hidx], el0);
                    atomicAdd(&g_er[(bz * Nn + row) * H + hidx], er0);
                }
                if (row + 8 < M) {
                    atomicAdd(&g_el[(bz * Nn + row + 8) * H + hidx], el1);
                    atomicAdd(&g_er[(bz * Nn + row + 8) * H + hidx], er1);
                }
            }
        }
    } else {
        // mode 1: w[row] += sum_col tanh(c + bias) * W2   (n0 == 0, Nd == 64)
        if (tid < 64) {
            sm[tid]      = bias[tid];
            sm[64 + tid] = W2p[tid];
        }
        __syncthreads();
#pragma unroll
        for (int mt = 0; mt < 4; mt++) {
            int row = m0 + wm * 64 + mt * 16 + gid;
            float w0 = 0.f, w1 = 0.f;
#pragma unroll
            for (int nt = 0; nt < 4; nt++) {
                int o = wn * 32 + nt * 8 + 2 * tig;
                float b0 = sm[o], b1v = sm[o + 1];
                float w2a = sm[64 + o], w2b = sm[64 + o + 1];
                w0 = fmaf(tanhf(c[mt][nt][0] + b0), w2a,
                     fmaf(tanhf(c[mt][nt][1] + b1v), w2b, w0));
                w1 = fmaf(tanhf(c[mt][nt][2] + b0), w2a,
                     fmaf(tanhf(c[mt][nt][3] + b1v), w2b, w1));
            }
#pragma unroll
            for (int off = 1; off <= 2; off <<= 1) {
                w0 += __shfl_xor_sync(0xFFFFFFFFu, w0, off);
                w1 += __shfl_xor_sync(0xFFFFFFFFu, w1, off);
            }
            if (tig == 0) {
                if (row < M)     atomicAdd(&g_w[bz * Nn + row], w0);
                if (row + 8 < M) atomicAdd(&g_w[bz * Nn + row + 8], w1);
            }
        }
    }
}

// ---------------- CSR build -------------------------------------------------------
__global__ void k_hist(const int* __restrict__ dstA) {
    int t = blockIdx.x * blockDim.x + threadIdx.x;
    if (t >= R * E) return;
    int r = t / E;
    atomicAdd(&g_cnt[r * Nn + dstA[t]], 1);
}

__global__ void k_scan() {   // one block (1024 thr) per relation; exclusive scan
    int r = blockIdx.x;
    __shared__ int sh[2048];
    __shared__ int carry;
    int t = threadIdx.x;
    if (t == 0) carry = 0;
    __syncthreads();
    const int* cnt = g_cnt + r * Nn;
    int* rp = g_rowptr + r * (Nn + 1);
    for (int base = 0; base < Nn; base += 1024) {
        int i = base + t;
        int v = (i < Nn) ? cnt[i] : 0;
        int pin = 0, pout = 1;
        sh[t] = v;
        __syncthreads();
        for (int off = 1; off < 1024; off <<= 1) {
            int x = sh[pin * 1024 + t];
            if (t >= off) x += sh[pin * 1024 + t - off];
            sh[pout * 1024 + t] = x;
            __syncthreads();
            pin ^= 1; pout ^= 1;
        }
        int incl = sh[pin * 1024 + t];
        if (i < Nn) rp[i] = carry + incl - v;   // exclusive
        __syncthreads();
        if (t == 1023) carry += incl;
        __syncthreads();
    }
    if (t == 0) rp[Nn] = carry;
}

__global__ void k_copy_cursor() {
    int t = blockIdx.x * blockDim.x + threadIdx.x;
    if (t >= R * Nn) return;
    int r = t / Nn, n = t % Nn;
    g_cursor[t] = g_rowptr[r * (Nn + 1) + n];
}

__global__ void k_scatter(const int* __restrict__ dstA) {
    int t = blockIdx.x * blockDim.x + threadIdx.x;
    if (t >= R * E) return;
    int r = t / E, e = t % E;
    int d = dstA[t];
    int p = atomicAdd(&g_cursor[r * Nn + d], 1);
    g_eid[(size_t)r * E + p] = e;
}

// ---------------- edge softmax: one thread per (r, dst, h) ------------------------
__global__ void k_softmax(const int* __restrict__ srcA) {
    int t = blockIdx.x * blockDim.x + threadIdx.x;
    if (t >= R * Nn * H) return;
    int h = t % H;
    int n = (t / H) % Nn;
    int r = t / (H * Nn);
    int s0 = g_rowptr[r * (Nn + 1) + n];
    int s1 = g_rowptr[r * (Nn + 1) + n + 1];
    if (s1 == s0) return;
    float erv = g_er[t];
    const int* src = srcA + (size_t)r * E;
    const int* eid = g_eid + (size_t)r * E;
    float* attn = g_attn + (size_t)r * E * H;

    float m = -3.4e38f;
    for (int p = s0; p < s1; p++) {
        int e = eid[p];
        float s = g_el[(src[e] + r * Nn) * H + h] + erv;
        s = (s > 0.f) ? s : 0.2f * s;
        attn[(size_t)p * H + h] = s;
        m = fmaxf(m, s);
    }
    float den = 0.f;
    for (int p = s0; p < s1; p++) {
        float ex = expf(attn[(size_t)p * H + h] - m);
        attn[(size_t)p * H + h] = ex;
        den += ex;
    }
    float inv = 1.f / den;
    for (int p = s0; p < s1; p++)
        attn[(size_t)p * H + h] *= inv;
}

// ---------------- aggregate: one 128-thread block per (r, dst) --------------------
__global__ void k_aggregate(const int* __restrict__ srcA, const float* __restrict__ bias) {
    int n = blockIdx.x;
    int r = blockIdx.y;
    int tid = threadIdx.x;       // 128
    int col = tid * 4;
    int h = tid >> 4;
    int s0 = g_rowptr[r * (Nn + 1) + n];
    int s1 = g_rowptr[r * (Nn + 1) + n + 1];
    const int* src = srcA + (size_t)r * E;
    const int* eid = g_eid + (size_t)r * E;
    const float* attn = g_attn + (size_t)r * E * H;
    const float* hb = g_h + (size_t)r * Nn * D;

    float a0 = 0.f, a1 = 0.f, a2 = 0.f, a3 = 0.f;
    int p = s0;
    for (; p + 1 < s1; p += 2) {
        int e0 = eid[p], e1 = eid[p + 1];
        int sn0 = src[e0], sn1 = src[e1];
        float w0 = attn[(size_t)p * H + h];
        float w1 = attn[(size_t)(p + 1) * H + h];
        float4 v0 = *(const float4*)(hb + (size_t)sn0 * D + col);
        float4 v1 = *(const float4*)(hb + (size_t)sn1 * D + col);
        a0 = fmaf(w0, v0.x, a0); a1 = fmaf(w0, v0.y, a1);
        a2 = fmaf(w0, v0.z, a2); a3 = fmaf(w0, v0.w, a3);
        a0 = fmaf(w1, v1.x, a0); a1 = fmaf(w1, v1.y, a1);
        a2 = fmaf(w1, v1.z, a2); a3 = fmaf(w1, v1.w, a3);
    }
    if (p < s1) {
        int e = eid[p];
        int sn = src[e];
        float w = attn[(size_t)p * H + h];
        float4 v = *(const float4*)(hb + (size_t)sn * D + col);
        a0 = fmaf(w, v.x, a0); a1 = fmaf(w, v.y, a1);
        a2 = fmaf(w, v.z, a2); a3 = fmaf(w, v.w, a3);
    }
    float4 bv = *(const float4*)(bias + r * D + col);
    float4 o;
    o.x = fminf(fmaxf(a0 + bv.x, 0.f), 6.f);
    o.y = fminf(fmaxf(a1 + bv.y, 0.f), 6.f);
    o.z = fminf(fmaxf(a2 + bv.z, 0.f), 6.f);
    o.w = fminf(fmaxf(a3 + bv.w, 0.f), 6.f);
    *(float4*)(g_z + ((size_t)(r * Nn + n)) * D + col) = o;
}

// ---------------- deterministic mean over nodes -----------------------------------
__global__ void k_wreduce() {
    int r = blockIdx.x;
    __shared__ float sh[1024];
    float s = 0.f;
    for (int i = threadIdx.x; i < Nn; i += 1024) s += g_w[r * Nn + i];
    sh[threadIdx.x] = s;
    __syncthreads();
    for (int off = 512; off > 0; off >>= 1) {
        if (threadIdx.x < off) sh[threadIdx.x] += sh[threadIdx.x + off];
        __syncthreads();
    }
    if (threadIdx.x == 0) g_wmean[r] = sh[0] / (float)Nn;
}

__global__ void k_beta() {
    if (threadIdx.x == 0) {
        float m = fmaxf(g_wmean[0], fmaxf(g_wmean[1], g_wmean[2]));
        float e0 = expf(g_wmean[0] - m);
        float e1 = expf(g_wmean[1] - m);
        float e2 = expf(g_wmean[2] - m);
        float inv = 1.f / (e0 + e1 + e2);
        g_beta[0] = e0 * inv;
        g_beta[1] = e1 * inv;
        g_beta[2] = e2 * inv;
    }
}

// ---------------- out = sum_r beta[r] * z[:, r, :] --------------------------------
__global__ void k_out(float* __restrict__ out) {
    int i = blockIdx.x * blockDim.x + threadIdx.x;
    if (i >= Nn * D / 4) return;
    float b0 = g_beta[0], b1 = g_beta[1], b2 = g_beta[2];
    const float4* z0 = (const float4*)g_z;
    const float4* z1 = (const float4*)(g_z + (size_t)Nn * D);
    const float4* z2 = (const float4*)(g_z + (size_t)2 * Nn * D);
    float4 v0 = z0[i], v1 = z1[i], v2 = z2[i];
    float4 o;
    o.x = b0 * v0.x + b1 * v1.x + b2 * v2.x;
    o.y = b0 * v0.y + b1 * v1.y + b2 * v2.y;
    o.z = b0 * v0.z + b1 * v1.z + b2 * v2.z;
    o.w = b0 * v0.w + b1 * v1.w + b2 * v2.w;
    ((float4*)out)[i] = o;
}

// ---------------- host ------------------------------------------------------------
extern "C" void kernel_launch(void* const* d_in, const int* in_sizes, int n_in,
                              void* d_out, int out_size) {
    const float* feats = (const float*)d_in[0];
    const int*   src   = (const int*)d_in[1];
    const int*   dst   = (const int*)d_in[2];
    const float* W     = (const float*)d_in[3];
    const float* al    = (const float*)d_in[4];
    const float* ar    = (const float*)d_in[5];
    const float* bias  = (const float*)d_in[6];
    const float* W1    = (const float*)d_in[7];
    const float* b1    = (const float*)d_in[8];
    const float* W2    = (const float*)d_in[9];
    float* out = (float*)d_out;

    float *hptr, *zptr;
    cudaGetSymbolAddress((void**)&hptr, g_h);
    cudaGetSymbolAddress((void**)&zptr, g_z);

    cudaFuncSetAttribute(k_gemm_tc, cudaFuncAttributeMaxDynamicSharedMemorySize,
                         (int)GSMEM);

    // zero accumulators (el/er/w/cnt) BEFORE fused GEMM1
    k_zero<<<(R * Nn * H + 255) / 256, 256>>>();

    // GEMM1: h[r] = feats[r] @ W[r]  + fused el/er epilogue
    k_gemm_tc<<<dim3((Nn + GBM - 1) / GBM, D / GBN, R), 128, GSMEM>>>(
        feats, W, hptr, al, ar, nullptr, nullptr,
        Nn, F, D, (size_t)Nn * F, (size_t)F * D, (size_t)Nn * D, 0);

    // CSR build
    k_hist<<<(R * E + 255) / 256, 256>>>(dst);
    k_scan<<<R, 1024>>>();
    k_copy_cursor<<<(R * Nn + 255) / 256, 256>>>();
    k_scatter<<<(R * E + 255) / 256, 256>>>(dst);

    // edge softmax + aggregate
    k_softmax<<<(R * Nn * H + 255) / 256, 256>>>(src);
    k_aggregate<<<dim3(Nn, R), 128>>>(src, bias);

    // path attention: fused tanh(z@W1+b1)@W2 -> g_w (no t materialization)
    k_gemm_tc<<<dim3((Nn + GBM - 1) / GBM, 1, R), 128, GSMEM>>>(
        zptr, W1, nullptr, nullptr, nullptr, b1, W2,
        Nn, D, O, (size_t)Nn * D, 0, 0, 1);

    k_wreduce<<<R, 1024>>>();
    k_beta<<<1, 32>>>();
    k_out<<<(Nn * D / 4 + 255) / 256, 256>>>(out);
}

// round 5
// speedup vs baseline: 2.1595x; 1.1180x over previous
#include <cuda_runtime.h>
#include <cuda_bf16.h>
#include <cuda_fp16.h>
#include <math.h>

#define R  3
#define Nn 20000
#define E  320000
#define F  256
#define H  8
#define O  64
#define D  512          // H*O
#define NCHUNK 20       // scan chunks per relation (20*1024 >= Nn)

// ---------------- scratch (static device globals; no allocations) ----------------
__device__ __half g_h16[(size_t)R * Nn * D];     // projected features (fp16, gather-only)
__device__ float g_z[(size_t)R * Nn * D];        // GAT output per relation (post relu6)
__device__ float g_el[R * Nn * H];
__device__ float g_er[R * Nn * H];
__device__ int   g_cnt[R * Nn];
__device__ int   g_rowptr[R * (Nn + 1)];
__device__ int   g_cursor[R * Nn];
__device__ int   g_bsum[R * NCHUNK];
__device__ int   g_boff[R * NCHUNK];
__device__ int   g_eid[(size_t)R * E];
__device__ float g_attn[(size_t)R * E * H];
__device__ float g_w[R * Nn];
__device__ float g_wmean[R];
__device__ float g_beta[R];

// ---------------- zero scratch accumulators ----------------
__global__ void k_zero() {
    int t = blockIdx.x * blockDim.x + threadIdx.x;
    if (t < R * Nn) { g_cnt[t] = 0; g_w[t] = 0.f; }
    if (t < R * Nn * H) { g_el[t] = 0.f; g_er[t] = 0.f; }
}

// ================= TF32 tensor-core GEMM (fused epilogues) ========================
// mode 0: C16 = h (fp16), and accumulate el/er = h . al/ar per (row, head=blockIdx.y)
// mode 1: no C store; w[row] += sum_col tanh(acc+bias[col]) * W2[col]
#define GBM 128
#define GBN 64
#define GBK 32
#define AST 36
#define BST 72
#define ASZ (GBM * AST)
#define BSZ (GBK * BST)
#define GSMEM (2 * (ASZ + BSZ) * sizeof(float))   // 55296 B

__device__ __forceinline__ float tf32r(float x) {
    float y;
    asm("cvt.rna.tf32.f32 %0, %1;" : "=f"(y) : "f"(x));
    return y;
}
__device__ __forceinline__ float4 cvt4(float4 v) {
    return make_float4(tf32r(v.x), tf32r(v.y), tf32r(v.z), tf32r(v.w));
}

__global__ void __launch_bounds__(128, 3) k_gemm_tc(
    const float* __restrict__ A0, const float* __restrict__ B0,
    __half* __restrict__ C16,
    const float* __restrict__ alp, const float* __restrict__ arp,   // mode 0
    const float* __restrict__ bias, const float* __restrict__ W2p,  // mode 1
    int M, int K, int Nd,
    size_t sA, size_t sB, size_t sC, int mode)
{
    extern __shared__ float sm[];
    float* Asb[2] = {sm, sm + ASZ};
    float* Bsb[2] = {sm + 2 * ASZ, sm + 2 * ASZ + BSZ};

    const int bz = blockIdx.z;
    const float* A = A0 + (size_t)bz * sA;
    const float* B = B0 + (size_t)bz * sB;

    const int tid  = threadIdx.x;                 // 128
    const int lane = tid & 31, wid = tid >> 5;    // 4 warps
    const int gid  = lane >> 2, tig = lane & 3;
    const int wm   = wid >> 1, wn = wid & 1;      // 2x2 warp grid, warp tile 64x32
    const int m0   = blockIdx.x * GBM, n0 = blockIdx.y * GBN;

    int aRow[8], aC[8];
#pragma unroll
    for (int i = 0; i < 8; i++) {
        int idx = tid + i * 128;
        aRow[i] = idx >> 3;
        aC[i]   = (idx & 7) * 4;
    }
    int bRow[4], bC[4];
#pragma unroll
    for (int i = 0; i < 4; i++) {
        int idx = tid + i * 128;
        bRow[i] = idx >> 4;
        bC[i]   = (idx & 15) * 4;
    }

    float c[4][4][4] = {};
    float4 sa[8], sb[4];

#pragma unroll
    for (int i = 0; i < 8; i++) {
        int gr = m0 + aRow[i];
        sa[i] = (gr < M) ? *(const float4*)(A + (size_t)gr * K + aC[i])
                         : make_float4(0.f, 0.f, 0.f, 0.f);
    }
#pragma unroll
    for (int i = 0; i < 4; i++)
        sb[i] = *(const float4*)(B + (size_t)bRow[i] * Nd + n0 + bC[i]);
#pragma unroll
    for (int i = 0; i < 8; i++)
        *(float4*)(Asb[0] + aRow[i] * AST + aC[i]) = cvt4(sa[i]);
#pragma unroll
    for (int i = 0; i < 4; i++)
        *(float4*)(Bsb[0] + bRow[i] * BST + bC[i]) = cvt4(sb[i]);
    __syncthreads();

    const int T = K / GBK;
    for (int it = 0; it < T; it++) {
        const int cur = it & 1;
        if (it + 1 < T) {
            const int k0n = (it + 1) * GBK;
#pragma unroll
            for (int i = 0; i < 8; i++) {
                int gr = m0 + aRow[i];
                sa[i] = (gr < M) ? *(const float4*)(A + (size_t)gr * K + k0n + aC[i])
                                 : make_float4(0.f, 0.f, 0.f, 0.f);
            }
#pragma unroll
            for (int i = 0; i < 4; i++)
                sb[i] = *(const float4*)(B + (size_t)(k0n + bRow[i]) * Nd + n0 + bC[i]);
        }

        const float* As = Asb[cur];
        const float* Bs = Bsb[cur];
#pragma unroll
        for (int kg = 0; kg < 4; kg++) {
            unsigned a[4][4], b[4][2];
#pragma unroll
            for (int mt = 0; mt < 4; mt++) {
                int rb = (wm * 64 + mt * 16 + gid) * AST + kg * 8 + tig;
                a[mt][0] = __float_as_uint(As[rb]);
                a[mt][1] = __float_as_uint(As[rb + 8 * AST]);
                a[mt][2] = __float_as_uint(As[rb + 4]);
                a[mt][3] = __float_as_uint(As[rb + 8 * AST + 4]);
            }
#pragma unroll
            for (int nt = 0; nt < 4; nt++) {
                int cb = (kg * 8 + tig) * BST + wn * 32 + nt * 8 + gid;
                b[nt][0] = __float_as_uint(Bs[cb]);
                b[nt][1] = __float_as_uint(Bs[cb + 4 * BST]);
            }
#pragma unroll
            for (int mt = 0; mt < 4; mt++)
#pragma unroll
                for (int nt = 0; nt < 4; nt++)
                    asm volatile(
                        "mma.sync.aligned.m16n8k8.row.col.f32.tf32.tf32.f32 "
                        "{%0,%1,%2,%3}, {%4,%5,%6,%7}, {%8,%9}, {%0,%1,%2,%3};"
                        : "+f"(c[mt][nt][0]), "+f"(c[mt][nt][1]),
                          "+f"(c[mt][nt][2]), "+f"(c[mt][nt][3])
                        : "r"(a[mt][0]), "r"(a[mt][1]), "r"(a[mt][2]), "r"(a[mt][3]),
                          "r"(b[nt][0]), "r"(b[nt][1]));
        }

        if (it + 1 < T) {
            float* Aw = Asb[cur ^ 1];
            float* Bw = Bsb[cur ^ 1];
#pragma unroll
            for (int i = 0; i < 8; i++)
                *(float4*)(Aw + aRow[i] * AST + aC[i]) = cvt4(sa[i]);
#pragma unroll
            for (int i = 0; i < 4; i++)
                *(float4*)(Bw + bRow[i] * BST + bC[i]) = cvt4(sb[i]);
        }
        __syncthreads();
    }

    // ---- epilogues ----
    if (mode == 0) {
        __half* C = C16 + (size_t)bz * sC;
        if (tid < 64) {
            sm[tid]      = alp[bz * D + n0 + tid];
            sm[64 + tid] = arp[bz * D + n0 + tid];
        }
        __syncthreads();
        const int hidx = blockIdx.y;
#pragma unroll
        for (int mt = 0; mt < 4; mt++) {
            int row = m0 + wm * 64 + mt * 16 + gid;
            float el0 = 0.f, er0 = 0.f, el1 = 0.f, er1 = 0.f;
#pragma unroll
            for (int nt = 0; nt < 4; nt++) {
                int o = wn * 32 + nt * 8 + 2 * tig;
                float al0 = sm[o], al1 = sm[o + 1];
                float ar0 = sm[64 + o], ar1 = sm[64 + o + 1];
                float v0 = c[mt][nt][0], v1 = c[mt][nt][1];
                float v2 = c[mt][nt][2], v3 = c[mt][nt][3];
                el0 = fmaf(v0, al0, fmaf(v1, al1, el0));
                er0 = fmaf(v0, ar0, fmaf(v1, ar1, er0));
                el1 = fmaf(v2, al0, fmaf(v3, al1, el1));
                er1 = fmaf(v2, ar0, fmaf(v3, ar1, er1));
                if (row < M)
                    *(__half2*)(C + (size_t)row * Nd + n0 + o) = __floats2half2_rn(v0, v1);
                if (row + 8 < M)
                    *(__half2*)(C + (size_t)(row + 8) * Nd + n0 + o) = __floats2half2_rn(v2, v3);
            }
#pragma unroll
            for (int off = 1; off <= 2; off <<= 1) {
                el0 += __shfl_xor_sync(0xFFFFFFFFu, el0, off);
                er0 += __shfl_xor_sync(0xFFFFFFFFu, er0, off);
                el1 += __shfl_xor_sync(0xFFFFFFFFu, el1, off);
                er1 += __shfl_xor_sync(0xFFFFFFFFu, er1, off);
            }
            if (tig == 0) {
                if (row < M) {
                    atomicAdd(&g_el[(bz * Nn + row) * H + hidx], el0);
                    atomicAdd(&g_er[(bz * Nn + row) * H + hidx], er0);
                }
                if (row + 8 < M) {
                    atomicAdd(&g_el[(bz * Nn + row + 8) * H + hidx], el1);
                    atomicAdd(&g_er[(bz * Nn + row + 8) * H + hidx], er1);
                }
            }
        }
    } else {
        if (tid < 64) {
            sm[tid]      = bias[tid];
            sm[64 + tid] = W2p[tid];
        }
        __syncthreads();
#pragma unroll
        for (int mt = 0; mt < 4; mt++) {
            int row = m0 + wm * 64 + mt * 16 + gid;
            float w0 = 0.f, w1 = 0.f;
#pragma unroll
            for (int nt = 0; nt < 4; nt++) {
                int o = wn * 32 + nt * 8 + 2 * tig;
                float b0 = sm[o], b1v = sm[o + 1];
                float w2a = sm[64 + o], w2b = sm[64 + o + 1];
                w0 = fmaf(tanhf(c[mt][nt][0] + b0), w2a,
                     fmaf(tanhf(c[mt][nt][1] + b1v), w2b, w0));
                w1 = fmaf(tanhf(c[mt][nt][2] + b0), w2a,
                     fmaf(tanhf(c[mt][nt][3] + b1v), w2b, w1));
            }
#pragma unroll
            for (int off = 1; off <= 2; off <<= 1) {
                w0 += __shfl_xor_sync(0xFFFFFFFFu, w0, off);
                w1 += __shfl_xor_sync(0xFFFFFFFFu, w1, off);
            }
            if (tig == 0) {
                if (row < M)     atomicAdd(&g_w[bz * Nn + row], w0);
                if (row + 8 < M) atomicAdd(&g_w[bz * Nn + row + 8], w1);
            }
        }
    }
}

// ---------------- CSR build -------------------------------------------------------
__global__ void k_hist(const int* __restrict__ dstA) {
    int t = blockIdx.x * blockDim.x + threadIdx.x;
    if (t >= R * E) return;
    int r = t / E;
    atomicAdd(&g_cnt[r * Nn + dstA[t]], 1);
}

// phase 1: per-1024-chunk local exclusive scan (256 thr, 4 elem/thr)
__global__ void k_scan1() {
    int chunk = blockIdx.x, r = blockIdx.y;
    int t = threadIdx.x;
    __shared__ int ws[8];
    int base = chunk * 1024 + t * 4;
    const int* cnt = g_cnt + r * Nn;
    int v[4];
#pragma unroll
    for (int j = 0; j < 4; j++) {
        int i = base + j;
        v[j] = (i < Nn) ? cnt[i] : 0;
    }
    int s = v[0] + v[1] + v[2] + v[3];
    // warp inclusive scan of s
    int lane = t & 31, w = t >> 5;
    int x = s;
#pragma unroll
    for (int off = 1; off < 32; off <<= 1) {
        int y = __shfl_up_sync(0xFFFFFFFFu, x, off);
        if (lane >= off) x += y;
    }
    if (lane == 31) ws[w] = x;
    __syncthreads();
    if (t < 8) {
        int y = ws[t];
#pragma unroll
        for (int off = 1; off < 8; off <<= 1) {
            int z = __shfl_up_sync(0xFFu, y, off);
            if (t >= off) y += z;
        }
        ws[t] = y;
    }
    __syncthreads();
    int excl = x - s + (w > 0 ? ws[w - 1] : 0);
    int* rp = g_rowptr + r * (Nn + 1);
    int run = excl;
#pragma unroll
    for (int j = 0; j < 4; j++) {
        int i = base + j;
        if (i < Nn) rp[i] = run;
        run += v[j];
    }
    if (t == 255) g_bsum[r * NCHUNK + chunk] = excl + s;   // chunk total
}

// phase 2: scan chunk totals (tiny)
__global__ void k_scan2() {
    int r = threadIdx.x;
    if (r >= R) return;
    int acc = 0;
    for (int c = 0; c < NCHUNK; c++) {
        g_boff[r * NCHUNK + c] = acc;
        acc += g_bsum[r * NCHUNK + c];
    }
}

// phase 3: add chunk offsets, write cursor, finalize rp[Nn]
__global__ void k_scan3() {
    int chunk = blockIdx.x, r = blockIdx.y;
    int t = threadIdx.x;
    int off = g_boff[r * NCHUNK + chunk];
    int* rp = g_rowptr + r * (Nn + 1);
#pragma unroll
    for (int j = 0; j < 4; j++) {
        int i = chunk * 1024 + t * 4 + j;
        if (i < Nn) {
            int val = rp[i] + off;
            rp[i] = val;
            g_cursor[r * Nn + i] = val;
        }
    }
    if (chunk == 0 && t == 0) rp[Nn] = E;
}

__global__ void k_scatter(const int* __restrict__ dstA) {
    int t = blockIdx.x * blockDim.x + threadIdx.x;
    if (t >= R * E) return;
    int r = t / E, e = t % E;
    int d = dstA[t];
    int p = atomicAdd(&g_cursor[r * Nn + d], 1);
    g_eid[(size_t)r * E + p] = e;
}

// ---------------- edge softmax: one thread per (r, dst, h) ------------------------
__global__ void k_softmax(const int* __restrict__ srcA) {
    int t = blockIdx.x * blockDim.x + threadIdx.x;
    if (t >= R * Nn * H) return;
    int h = t % H;
    int n = (t / H) % Nn;
    int r = t / (H * Nn);
    int s0 = g_rowptr[r * (Nn + 1) + n];
    int s1 = g_rowptr[r * (Nn + 1) + n + 1];
    if (s1 == s0) return;
    float erv = g_er[t];
    const int* src = srcA + (size_t)r * E;
    const int* eid = g_eid + (size_t)r * E;
    float* attn = g_attn + (size_t)r * E * H;

    float m = -3.4e38f;
    for (int p = s0; p < s1; p++) {
        int e = eid[p];
        float s = g_el[(src[e] + r * Nn) * H + h] + erv;
        s = (s > 0.f) ? s : 0.2f * s;
        attn[(size_t)p * H + h] = s;
        m = fmaxf(m, s);
    }
    float den = 0.f;
    for (int p = s0; p < s1; p++) {
        float ex = expf(attn[(size_t)p * H + h] - m);
        attn[(size_t)p * H + h] = ex;
        den += ex;
    }
    float inv = 1.f / den;
    for (int p = s0; p < s1; p++)
        attn[(size_t)p * H + h] *= inv;
}

// ---------------- aggregate: one 128-thread block per (r, dst), fp16 h ------------
__global__ void k_aggregate(const int* __restrict__ srcA, const float* __restrict__ bias) {
    int n = blockIdx.x;
    int r = blockIdx.y;
    int tid = threadIdx.x;       // 128
    int col = tid * 4;
    int h = tid >> 4;
    int s0 = g_rowptr[r * (Nn + 1) + n];
    int s1 = g_rowptr[r * (Nn + 1) + n + 1];
    const int* src = srcA + (size_t)r * E;
    const int* eid = g_eid + (size_t)r * E;
    const float* attn = g_attn + (size_t)r * E * H;
    const __half* hb = g_h16 + (size_t)r * Nn * D;

    float a0 = 0.f, a1 = 0.f, a2 = 0.f, a3 = 0.f;
    int p = s0;
    for (; p + 1 < s1; p += 2) {
        int e0 = eid[p], e1 = eid[p + 1];
        int sn0 = src[e0], sn1 = src[e1];
        float w0 = attn[(size_t)p * H + h];
        float w1 = attn[(size_t)(p + 1) * H + h];
        const __half2* q0 = (const __half2*)(hb + (size_t)sn0 * D + col);
        const __half2* q1 = (const __half2*)(hb + (size_t)sn1 * D + col);
        float2 u0 = __half22float2(q0[0]), u1 = __half22float2(q0[1]);
        float2 v0 = __half22float2(q1[0]), v1 = __half22float2(q1[1]);
        a0 = fmaf(w0, u0.x, a0); a1 = fmaf(w0, u0.y, a1);
        a2 = fmaf(w0, u1.x, a2); a3 = fmaf(w0, u1.y, a3);
        a0 = fmaf(w1, v0.x, a0); a1 = fmaf(w1, v0.y, a1);
        a2 = fmaf(w1, v1.x, a2); a3 = fmaf(w1, v1.y, a3);
    }
    if (p < s1) {
        int e = eid[p];
        int sn = src[e];
        float w = attn[(size_t)p * H + h];
        const __half2* q = (const __half2*)(hb + (size_t)sn * D + col);
        float2 u0 = __half22float2(q[0]), u1 = __half22float2(q[1]);
        a0 = fmaf(w, u0.x, a0); a1 = fmaf(w, u0.y, a1);
        a2 = fmaf(w, u1.x, a2); a3 = fmaf(w, u1.y, a3);
    }
    float4 bv = *(const float4*)(bias + r * D + col);
    float4 o;
    o.x = fminf(fmaxf(a0 + bv.x, 0.f), 6.f);
    o.y = fminf(fmaxf(a1 + bv.y, 0.f), 6.f);
    o.z = fminf(fmaxf(a2 + bv.z, 0.f), 6.f);
    o.w = fminf(fmaxf(a3 + bv.w, 0.f), 6.f);
    *(float4*)(g_z + ((size_t)(r * Nn + n)) * D + col) = o;
}

// ---------------- deterministic mean over nodes -----------------------------------
__global__ void k_wreduce() {
    int r = blockIdx.x;
    __shared__ float sh[1024];
    float s = 0.f;
    for (int i = threadIdx.x; i < Nn; i += 1024) s += g_w[r * Nn + i];
    sh[threadIdx.x] = s;
    __syncthreads();
    for (int off = 512; off > 0; off >>= 1) {
        if (threadIdx.x < off) sh[threadIdx.x] += sh[threadIdx.x + off];
        __syncthreads();
    }
    if (threadIdx.x == 0) g_wmean[r] = sh[0] / (float)Nn;
}

__global__ void k_beta() {
    if (threadIdx.x == 0) {
        float m = fmaxf(g_wmean[0], fmaxf(g_wmean[1], g_wmean[2]));
        float e0 = expf(g_wmean[0] - m);
        float e1 = expf(g_wmean[1] - m);
        float e2 = expf(g_wmean[2] - m);
        float inv = 1.f / (e0 + e1 + e2);
        g_beta[0] = e0 * inv;
        g_beta[1] = e1 * inv;
        g_beta[2] = e2 * inv;
    }
}

// ---------------- out = sum_r beta[r] * z[:, r, :] --------------------------------
__global__ void k_out(float* __restrict__ out) {
    int i = blockIdx.x * blockDim.x + threadIdx.x;
    if (i >= Nn * D / 4) return;
    float b0 = g_beta[0], b1 = g_beta[1], b2 = g_beta[2];
    const float4* z0 = (const float4*)g_z;
    const float4* z1 = (const float4*)(g_z + (size_t)Nn * D);
    const float4* z2 = (const float4*)(g_z + (size_t)2 * Nn * D);
    float4 v0 = z0[i], v1 = z1[i], v2 = z2[i];
    float4 o;
    o.x = b0 * v0.x + b1 * v1.x + b2 * v2.x;
    o.y = b0 * v0.y + b1 * v1.y + b2 * v2.y;
    o.z = b0 * v0.z + b1 * v1.z + b2 * v2.z;
    o.w = b0 * v0.w + b1 * v1.w + b2 * v2.w;
    ((float4*)out)[i] = o;
}

// ---------------- host ------------------------------------------------------------
extern "C" void kernel_launch(void* const* d_in, const int* in_sizes, int n_in,
                              void* d_out, int out_size) {
    const float* feats = (const float*)d_in[0];
    const int*   src   = (const int*)d_in[1];
    const int*   dst   = (const int*)d_in[2];
    const float* W     = (const float*)d_in[3];
    const float* al    = (const float*)d_in[4];
    const float* ar    = (const float*)d_in[5];
    const float* bias  = (const float*)d_in[6];
    const float* W1    = (const float*)d_in[7];
    const float* b1    = (const float*)d_in[8];
    const float* W2    = (const float*)d_in[9];
    float* out = (float*)d_out;

    __half* hptr;
    float* zptr;
    cudaGetSymbolAddress((void**)&hptr, g_h16);
    cudaGetSymbolAddress((void**)&zptr, g_z);

    cudaFuncSetAttribute(k_gemm_tc, cudaFuncAttributeMaxDynamicSharedMemorySize,
                         (int)GSMEM);

    k_zero<<<(R * Nn * H + 255) / 256, 256>>>();

    // GEMM1: h[r] = feats[r] @ W[r]  (fp16 store) + fused el/er epilogue
    k_gemm_tc<<<dim3((Nn + GBM - 1) / GBM, D / GBN, R), 128, GSMEM>>>(
        feats, W, hptr, al, ar, nullptr, nullptr,
        Nn, F, D, (size_t)Nn * F, (size_t)F * D, (size_t)Nn * D, 0);

    // CSR build (parallel scan, fused cursor)
    k_hist<<<(R * E + 255) / 256, 256>>>(dst);
    k_scan1<<<dim3(NCHUNK, R), 256>>>();
    k_scan2<<<1, 32>>>();
    k_scan3<<<dim3(NCHUNK, R), 256>>>();
    k_scatter<<<(R * E + 255) / 256, 256>>>(dst);

    // edge softmax + aggregate
    k_softmax<<<(R * Nn * H + 255) / 256, 256>>>(src);
    k_aggregate<<<dim3(Nn, R), 128>>>(src, bias);

    // path attention: fused tanh(z@W1+b1)@W2 -> g_w
    k_gemm_tc<<<dim3((Nn + GBM - 1) / GBM, 1, R), 128, GSMEM>>>(
        zptr, W1, nullptr, nullptr, nullptr, b1, W2,
        Nn, D, O, (size_t)Nn * D, 0, 0, 1);

    k_wreduce<<<R, 1024>>>();
    k_beta<<<1, 32>>>();
    k_out<<<(Nn * D / 4 + 255) / 256, 256>>>(out);
}

// round 8
// speedup vs baseline: 2.6007x; 1.2043x over previous
#include <cuda_runtime.h>
#include <cuda_fp16.h>
#include <stdint.h>
#include <math.h>

#define R  3
#define Nn 20000
#define E  320000
#define F  256
#define H  8
#define O  64
#define D  512
#define NCHUNK 20

// ---------------- scratch (static device globals; no allocations) ----------------
__device__ __half g_h16[(size_t)R * Nn * D];
__device__ float g_z[(size_t)R * Nn * D];
__device__ float g_el[R * Nn * H];
__device__ float g_er[R * Nn * H];
__device__ int   g_cnt[R * Nn];
__device__ int   g_rowptr[R * (Nn + 1)];
__device__ int   g_cursor[R * Nn];
__device__ int   g_bsum[R * NCHUNK];
__device__ int   g_boff[R * NCHUNK];
__device__ int   g_eid[(size_t)R * E];
__device__ float g_attn[(size_t)R * E * H];
__device__ float g_w[R * Nn];
__device__ float g_wmean[R];
__device__ float g_beta[R];

// ---------------- zero scratch accumulators ----------------
__global__ void k_zero() {
    int t = blockIdx.x * blockDim.x + threadIdx.x;
    if (t < R * Nn) { g_cnt[t] = 0; g_w[t] = 0.f; }
    if (t < R * Nn * H) { g_el[t] = 0.f; g_er[t] = 0.f; }
}

// ================= FP16 tensor-core GEMM (ldmatrix + m16n8k16) ====================
#define GBM 128
#define GBN 64
#define GBK 32
#define AST2 40
#define BST2 72
#define ASZ2 (GBM * AST2)
#define BSZ2 (GBK * BST2)
#define GSMEM (2 * (ASZ2 + BSZ2) * (int)sizeof(__half))

union H4 {
    float2 f2;
    __half2 h2[2];
};

__device__ __forceinline__ void ldsm4(unsigned* r, unsigned addr) {
    asm volatile("ldmatrix.sync.aligned.m8n8.x4.shared.b16 {%0,%1,%2,%3}, [%4];"
                 : "=r"(r[0]), "=r"(r[1]), "=r"(r[2]), "=r"(r[3]) : "r"(addr));
}
__device__ __forceinline__ void ldsm4t(unsigned* r, unsigned addr) {
    asm volatile("ldmatrix.sync.aligned.m8n8.x4.trans.shared.b16 {%0,%1,%2,%3}, [%4];"
                 : "=r"(r[0]), "=r"(r[1]), "=r"(r[2]), "=r"(r[3]) : "r"(addr));
}
__device__ __forceinline__ float2 f4_to_h4(float4 v) {
    H4 u;
    u.h2[0] = __floats2half2_rn(v.x, v.y);
    u.h2[1] = __floats2half2_rn(v.z, v.w);
    return u.f2;
}

__global__ void __launch_bounds__(128, 3) k_gemm_tc(
    const float* __restrict__ A0, const float* __restrict__ B0,
    __half* __restrict__ C16,
    const float* __restrict__ alp, const float* __restrict__ arp,
    const float* __restrict__ bias, const float* __restrict__ W2p,
    int M, int K, int Nd,
    size_t sA, size_t sB, size_t sC, int mode)
{
    extern __shared__ __half hsm[];
    __half* Asb0 = hsm;
    __half* Asb1 = hsm + ASZ2;
    __half* Bsb0 = hsm + 2 * ASZ2;
    __half* Bsb1 = hsm + 2 * ASZ2 + BSZ2;
    float* fsm = (float*)hsm;

    const int bz = blockIdx.z;
    const float* A = A0 + (size_t)bz * sA;
    const float* B = B0 + (size_t)bz * sB;

    const int tid  = threadIdx.x;
    const int lane = tid & 31, wid = tid >> 5;
    const int gid  = lane >> 2, tig = lane & 3;
    const int wm   = wid >> 1, wn = wid & 1;
    const int m0   = blockIdx.x * GBM, n0 = blockIdx.y * GBN;

    const unsigned uA0 = (unsigned)__cvta_generic_to_shared(Asb0);
    const unsigned uA1 = (unsigned)__cvta_generic_to_shared(Asb1);
    const unsigned uB0 = (unsigned)__cvta_generic_to_shared(Bsb0);
    const unsigned uB1 = (unsigned)__cvta_generic_to_shared(Bsb1);

    int aRow[8], aC[8];
#pragma unroll
    for (int i = 0; i < 8; i++) {
        int idx = tid + i * 128;
        aRow[i] = idx >> 3;
        aC[i]   = (idx & 7) * 4;
    }
    int bRow[4], bC[4];
#pragma unroll
    for (int i = 0; i < 4; i++) {
        int idx = tid + i * 128;
        bRow[i] = idx >> 4;
        bC[i]   = (idx & 15) * 4;
    }

    const int aLRow = lane & 15, aLSel = lane >> 4;
    const int bLRow = lane & 15, bLSel = lane >> 4;

    float c[4][4][4];
#pragma unroll
    for (int i = 0; i < 4; i++)
#pragma unroll
        for (int j = 0; j < 4; j++) {
            c[i][j][0] = 0.f; c[i][j][1] = 0.f;
            c[i][j][2] = 0.f; c[i][j][3] = 0.f;
        }

    float4 sa[8], sb[4];

    // prologue: tile 0
#pragma unroll
    for (int i = 0; i < 8; i++) {
        int gr = m0 + aRow[i];
        sa[i] = (gr < M) ? *(const float4*)(A + (size_t)gr * K + aC[i])
                         : make_float4(0.f, 0.f, 0.f, 0.f);
    }
#pragma unroll
    for (int i = 0; i < 4; i++)
        sb[i] = *(const float4*)(B + (size_t)bRow[i] * Nd + n0 + bC[i]);
#pragma unroll
    for (int i = 0; i < 8; i++)
        *(float2*)(Asb0 + aRow[i] * AST2 + aC[i]) = f4_to_h4(sa[i]);
#pragma unroll
    for (int i = 0; i < 4; i++)
        *(float2*)(Bsb0 + bRow[i] * BST2 + bC[i]) = f4_to_h4(sb[i]);
    __syncthreads();

    const int T = K / GBK;
    for (int it = 0; it < T; it++) {
        const int cur = it & 1;
        if (it + 1 < T) {
            const int k0n = (it + 1) * GBK;
#pragma unroll
            for (int i = 0; i < 8; i++) {
                int gr = m0 + aRow[i];
                sa[i] = (gr < M) ? *(const float4*)(A + (size_t)gr * K + k0n + aC[i])
                                 : make_float4(0.f, 0.f, 0.f, 0.f);
            }
#pragma unroll
            for (int i = 0; i < 4; i++)
                sb[i] = *(const float4*)(B + (size_t)(k0n + bRow[i]) * Nd + n0 + bC[i]);
        }

        const unsigned uAc = cur ? uA1 : uA0;
        const unsigned uBc = cur ? uB1 : uB0;
#pragma unroll
        for (int kg = 0; kg < 2; kg++) {
            unsigned a[4][4], b[2][4];
#pragma unroll
            for (int mt = 0; mt < 4; mt++) {
                int row = wm * 64 + mt * 16 + aLRow;
                int ch  = kg * 16 + aLSel * 8;
                ldsm4(a[mt], uAc + (unsigned)(row * AST2 + ch) * 2u);
            }
#pragma unroll
            for (int nt2 = 0; nt2 < 2; nt2++) {
                int krow = kg * 16 + bLRow;
                int ncol = wn * 32 + nt2 * 16 + bLSel * 8;
                ldsm4t(b[nt2], uBc + (unsigned)(krow * BST2 + ncol) * 2u);
            }
#pragma unroll
            for (int mt = 0; mt < 4; mt++) {
#pragma unroll
                for (int nt = 0; nt < 4; nt++) {
                    unsigned bb0 = b[nt >> 1][(nt & 1) * 2];
                    unsigned bb1 = b[nt >> 1][(nt & 1) * 2 + 1];
                    asm volatile(
                        "mma.sync.aligned.m16n8k16.row.col.f32.f16.f16.f32 "
                        "{%0,%1,%2,%3}, {%4,%5,%6,%7}, {%8,%9}, {%0,%1,%2,%3};"
                        : "+f"(c[mt][nt][0]), "+f"(c[mt][nt][1]),
                          "+f"(c[mt][nt][2]), "+f"(c[mt][nt][3])
                        : "r"(a[mt][0]), "r"(a[mt][1]), "r"(a[mt][2]), "r"(a[mt][3]),
                          "r"(bb0), "r"(bb1));
                }
            }
        }

        if (it + 1 < T) {
            __half* Aw = cur ? Asb0 : Asb1;
            __half* Bw = cur ? Bsb0 : Bsb1;
#pragma unroll
            for (int i = 0; i < 8; i++)
                *(float2*)(Aw + aRow[i] * AST2 + aC[i]) = f4_to_h4(sa[i]);
#pragma unroll
            for (int i = 0; i < 4; i++)
                *(float2*)(Bw + bRow[i] * BST2 + bC[i]) = f4_to_h4(sb[i]);
        }
        __syncthreads();
    }

    // ---- epilogues ----
    if (mode == 0) {
        __half* C = C16 + (size_t)bz * sC;
        if (tid < 64) {
            fsm[tid]      = alp[bz * D + n0 + tid];
            fsm[64 + tid] = arp[bz * D + n0 + tid];
        }
        __syncthreads();
        const int hidx = blockIdx.y;
#pragma unroll
        for (int mt = 0; mt < 4; mt++) {
            int row = m0 + wm * 64 + mt * 16 + gid;
            float el0 = 0.f, er0 = 0.f, el1 = 0.f, er1 = 0.f;
#pragma unroll
            for (int nt = 0; nt < 4; nt++) {
                int o = wn * 32 + nt * 8 + 2 * tig;
                float al0 = fsm[o], al1 = fsm[o + 1];
                float ar0 = fsm[64 + o], ar1 = fsm[64 + o + 1];
                float v0 = c[mt][nt][0], v1 = c[mt][nt][1];
                float v2 = c[mt][nt][2], v3 = c[mt][nt][3];
                el0 = fmaf(v0, al0, fmaf(v1, al1, el0));
                er0 = fmaf(v0, ar0, fmaf(v1, ar1, er0));
                el1 = fmaf(v2, al0, fmaf(v3, al1, el1));
                er1 = fmaf(v2, ar0, fmaf(v3, ar1, er1));
                if (row < M)
                    *(__half2*)(C + (size_t)row * Nd + n0 + o) = __floats2half2_rn(v0, v1);
                if (row + 8 < M)
                    *(__half2*)(C + (size_t)(row + 8) * Nd + n0 + o) = __floats2half2_rn(v2, v3);
            }
#pragma unroll
            for (int off = 1; off <= 2; off <<= 1) {
                el0 += __shfl_xor_sync(0xFFFFFFFFu, el0, off);
                er0 += __shfl_xor_sync(0xFFFFFFFFu, er0, off);
                el1 += __shfl_xor_sync(0xFFFFFFFFu, el1, off);
                er1 += __shfl_xor_sync(0xFFFFFFFFu, er1, off);
            }
            if (tig == 0) {
                if (row < M) {
                    atomicAdd(&g_el[(bz * Nn + row) * H + hidx], el0);
                    atomicAdd(&g_er[(bz * Nn + row) * H + hidx], er0);
                }
                if (row + 8 < M) {
                    atomicAdd(&g_el[(bz * Nn + row + 8) * H + hidx], el1);
                    atomicAdd(&g_er[(bz * Nn + row + 8) * H + hidx], er1);
                }
            }
        }
    } else {
        if (tid < 64) {
            fsm[tid]      = bias[tid];
            fsm[64 + tid] = W2p[tid];
        }
        __syncthreads();
#pragma unroll
        for (int mt = 0; mt < 4; mt++) {
            int row = m0 + wm * 64 + mt * 16 + gid;
            float w0 = 0.f, w1 = 0.f;
#pragma unroll
            for (int nt = 0; nt < 4; nt++) {
                int o = wn * 32 + nt * 8 + 2 * tig;
                float b0 = fsm[o], b1v = fsm[o + 1];
                float w2a = fsm[64 + o], w2b = fsm[64 + o + 1];
                w0 = fmaf(tanhf(c[mt][nt][0] + b0), w2a,
                     fmaf(tanhf(c[mt][nt][1] + b1v), w2b, w0));
                w1 = fmaf(tanhf(c[mt][nt][2] + b0), w2a,
                     fmaf(tanhf(c[mt][nt][3] + b1v), w2b, w1));
            }
#pragma unroll
            for (int off = 1; off <= 2; off <<= 1) {
                w0 += __shfl_xor_sync(0xFFFFFFFFu, w0, off);
                w1 += __shfl_xor_sync(0xFFFFFFFFu, w1, off);
            }
            if (tig == 0) {
                if (row < M)     atomicAdd(&g_w[bz * Nn + row], w0);
                if (row + 8 < M) atomicAdd(&g_w[bz * Nn + row + 8], w1);
            }
        }
    }
}

// ---------------- CSR build -------------------------------------------------------
__global__ void k_hist(const int* __restrict__ dstA) {
    int t = blockIdx.x * blockDim.x + threadIdx.x;
    if (t >= R * E) return;
    int r = t / E;
    atomicAdd(&g_cnt[r * Nn + dstA[t]], 1);
}

__global__ void k_scan1() {
    int chunk = blockIdx.x, r = blockIdx.y;
    int t = threadIdx.x;
    __shared__ int ws[8];
    int base = chunk * 1024 + t * 4;
    const int* cnt = g_cnt + r * Nn;
    int v[4];
#pragma unroll
    for (int j = 0; j < 4; j++) {
        int i = base + j;
        v[j] = (i < Nn) ? cnt[i] : 0;
    }
    int s = v[0] + v[1] + v[2] + v[3];
    int lane = t & 31, w = t >> 5;
    int x = s;
#pragma unroll
    for (int off = 1; off < 32; off <<= 1) {
        int y = __shfl_up_sync(0xFFFFFFFFu, x, off);
        if (lane >= off) x += y;
    }
    if (lane == 31) ws[w] = x;
    __syncthreads();
    if (t < 8) {
        int y = ws[t];
#pragma unroll
        for (int off = 1; off < 8; off <<= 1) {
            int z = __shfl_up_sync(0xFFu, y, off);
            if (t >= off) y += z;
        }
        ws[t] = y;
    }
    __syncthreads();
    int excl = x - s + (w > 0 ? ws[w - 1] : 0);
    int* rp = g_rowptr + r * (Nn + 1);
    int run = excl;
#pragma unroll
    for (int j = 0; j < 4; j++) {
        int i = base + j;
        if (i < Nn) rp[i] = run;
        run += v[j];
    }
    if (t == 255) g_bsum[r * NCHUNK + chunk] = excl + s;
}

__global__ void k_scan2() {
    int r = threadIdx.x;
    if (r >= R) return;
    int acc = 0;
    for (int c = 0; c < NCHUNK; c++) {
        g_boff[r * NCHUNK + c] = acc;
        acc += g_bsum[r * NCHUNK + c];
    }
}

__global__ void k_scan3() {
    int chunk = blockIdx.x, r = blockIdx.y;
    int t = threadIdx.x;
    int off = g_boff[r * NCHUNK + chunk];
    int* rp = g_rowptr + r * (Nn + 1);
#pragma unroll
    for (int j = 0; j < 4; j++) {
        int i = chunk * 1024 + t * 4 + j;
        if (i < Nn) {
            int val = rp[i] + off;
            rp[i] = val;
            g_cursor[r * Nn + i] = val;
        }
    }
    if (chunk == 0 && t == 0) rp[Nn] = E;
}

__global__ void k_scatter(const int* __restrict__ dstA) {
    int t = blockIdx.x * blockDim.x + threadIdx.x;
    if (t >= R * E) return;
    int r = t / E, e = t % E;
    int d = dstA[t];
    int p = atomicAdd(&g_cursor[r * Nn + d], 1);
    g_eid[(size_t)r * E + p] = e;
}

// ---------------- edge softmax ----------------------------------------------------
__global__ void k_softmax(const int* __restrict__ srcA) {
    int t = blockIdx.x * blockDim.x + threadIdx.x;
    if (t >= R * Nn * H) return;
    int h = t % H;
    int n = (t / H) % Nn;
    int r = t / (H * Nn);
    int s0 = g_rowptr[r * (Nn + 1) + n];
    int s1 = g_rowptr[r * (Nn + 1) + n + 1];
    if (s1 == s0) return;
    float erv = g_er[t];
    const int* src = srcA + (size_t)r * E;
    const int* eid = g_eid + (size_t)r * E;
    float* attn = g_attn + (size_t)r * E * H;

    float m = -3.4e38f;
    for (int p = s0; p < s1; p++) {
        int e = eid[p];
        float s = g_el[(src[e] + r * Nn) * H + h] + erv;
        s = (s > 0.f) ? s : 0.2f * s;
        attn[(size_t)p * H + h] = s;
        m = fmaxf(m, s);
    }
    float den = 0.f;
    for (int p = s0; p < s1; p++) {
        float ex = expf(attn[(size_t)p * H + h] - m);
        attn[(size_t)p * H + h] = ex;
        den += ex;
    }
    float inv = 1.f / den;
    for (int p = s0; p < s1; p++)
        attn[(size_t)p * H + h] *= inv;
}

// ---------------- aggregate -------------------------------------------------------
__global__ void k_aggregate(const int* __restrict__ srcA, const float* __restrict__ bias) {
    int n = blockIdx.x;
    int r = blockIdx.y;
    int tid = threadIdx.x;
    int col = tid * 4;
    int h = tid >> 4;
    int s0 = g_rowptr[r * (Nn + 1) + n];
    int s1 = g_rowptr[r * (Nn + 1) + n + 1];
    const int* src = srcA + (size_t)r * E;
    const int* eid = g_eid + (size_t)r * E;
    const float* attn = g_attn + (size_t)r * E * H;
    const __half* hb = g_h16 + (size_t)r * Nn * D;

    float a0 = 0.f, a1 = 0.f, a2 = 0.f, a3 = 0.f;
    int p = s0;
    for (; p + 1 < s1; p += 2) {
        int e0 = eid[p], e1 = eid[p + 1];
        int sn0 = src[e0], sn1 = src[e1];
        float w0 = attn[(size_t)p * H + h];
        float w1 = attn[(size_t)(p + 1) * H + h];
        const __half2* q0 = (const __half2*)(hb + (size_t)sn0 * D + col);
        const __half2* q1 = (const __half2*)(hb + (size_t)sn1 * D + col);
        float2 u0 = __half22float2(q0[0]), u1 = __half22float2(q0[1]);
        float2 v0 = __half22float2(q1[0]), v1 = __half22float2(q1[1]);
        a0 = fmaf(w0, u0.x, a0); a1 = fmaf(w0, u0.y, a1);
        a2 = fmaf(w0, u1.x, a2); a3 = fmaf(w0, u1.y, a3);
        a0 = fmaf(w1, v0.x, a0); a1 = fmaf(w1, v0.y, a1);
        a2 = fmaf(w1, v1.x, a2); a3 = fmaf(w1, v1.y, a3);
    }
    if (p < s1) {
        int e = eid[p];
        int sn = src[e];
        float w = attn[(size_t)p * H + h];
        const __half2* q = (const __half2*)(hb + (size_t)sn * D + col);
        float2 u0 = __half22float2(q[0]), u1 = __half22float2(q[1]);
        a0 = fmaf(w, u0.x, a0); a1 = fmaf(w, u0.y, a1);
        a2 = fmaf(w, u1.x, a2); a3 = fmaf(w, u1.y, a3);
    }
    float4 bv = *(const float4*)(bias + r * D + col);
    float4 o;
    o.x = fminf(fmaxf(a0 + bv.x, 0.f), 6.f);
    o.y = fminf(fmaxf(a1 + bv.y, 0.f), 6.f);
    o.z = fminf(fmaxf(a2 + bv.z, 0.f), 6.f);
    o.w = fminf(fmaxf(a3 + bv.w, 0.f), 6.f);
    *(float4*)(g_z + ((size_t)(r * Nn + n)) * D + col) = o;
}

// ---------------- deterministic mean over nodes -----------------------------------
__global__ void k_wreduce() {
    int r = blockIdx.x;
    __shared__ float sh[1024];
    float s = 0.f;
    for (int i = threadIdx.x; i < Nn; i += 1024) s += g_w[r * Nn + i];
    sh[threadIdx.x] = s;
    __syncthreads();
    for (int off = 512; off > 0; off >>= 1) {
        if (threadIdx.x < off) sh[threadIdx.x] += sh[threadIdx.x + off];
        __syncthreads();
    }
    if (threadIdx.x == 0) g_wmean[r] = sh[0] / (float)Nn;
}

__global__ void k_beta() {
    if (threadIdx.x == 0) {
        float m = fmaxf(g_wmean[0], fmaxf(g_wmean[1], g_wmean[2]));
        float e0 = expf(g_wmean[0] - m);
        float e1 = expf(g_wmean[1] - m);
        float e2 = expf(g_wmean[2] - m);
        float inv = 1.f / (e0 + e1 + e2);
        g_beta[0] = e0 * inv;
        g_beta[1] = e1 * inv;
        g_beta[2] = e2 * inv;
    }
}

// ---------------- out = sum_r beta[r] * z[:, r, :] --------------------------------
__global__ void k_out(float* __restrict__ out) {
    int i = blockIdx.x * blockDim.x + threadIdx.x;
    if (i >= Nn * D / 4) return;
    float b0 = g_beta[0], b1 = g_beta[1], b2 = g_beta[2];
    const float4* z0 = (const float4*)g_z;
    const float4* z1 = (const float4*)(g_z + (size_t)Nn * D);
    const float4* z2 = (const float4*)(g_z + (size_t)2 * Nn * D);
    float4 v0 = z0[i], v1 = z1[i], v2 = z2[i];
    float4 o;
    o.x = b0 * v0.x + b1 * v1.x + b2 * v2.x;
    o.y = b0 * v0.y + b1 * v1.y + b2 * v2.y;
    o.z = b0 * v0.z + b1 * v1.z + b2 * v2.z;
    o.w = b0 * v0.w + b1 * v1.w + b2 * v2.w;
    ((float4*)out)[i] = o;
}

// ---------------- host ------------------------------------------------------------
extern "C" void kernel_launch(void* const* d_in, const int* in_sizes, int n_in,
                              void* d_out, int out_size) {
    const float* feats = (const float*)d_in[0];
    const int*   src   = (const int*)d_in[1];
    const int*   dst   = (const int*)d_in[2];
    const float* W     = (const float*)d_in[3];
    const float* al    = (const float*)d_in[4];
    const float* ar    = (const float*)d_in[5];
    const float* bias  = (const float*)d_in[6];
    const float* W1    = (const float*)d_in[7];
    const float* b1    = (const float*)d_in[8];
    const float* W2    = (const float*)d_in[9];
    float* out = (float*)d_out;

    __half* hptr;
    float* zptr;
    cudaGetSymbolAddress((void**)&hptr, g_h16);
    cudaGetSymbolAddress((void**)&zptr, g_z);

    cudaFuncSetAttribute(k_gemm_tc, cudaFuncAttributeMaxDynamicSharedMemorySize,
                         GSMEM);

    k_zero<<<(R * Nn * H + 255) / 256, 256>>>();

    k_gemm_tc<<<dim3((Nn + GBM - 1) / GBM, D / GBN, R), 128, GSMEM>>>(
        feats, W, hptr, al, ar, (const float*)0, (const float*)0,
        Nn, F, D, (size_t)Nn * F, (size_t)F * D, (size_t)Nn * D, 0);

    k_hist<<<(R * E + 255) / 256, 256>>>(dst);
    k_scan1<<<dim3(NCHUNK, R), 256>>>();
    k_scan2<<<1, 32>>>();
    k_scan3<<<dim3(NCHUNK, R), 256>>>();
    k_scatter<<<(R * E + 255) / 256, 256>>>(dst);

    k_softmax<<<(R * Nn * H + 255) / 256, 256>>>(src);
    k_aggregate<<<dim3(Nn, R), 128>>>(src, bias);

    k_gemm_tc<<<dim3((Nn + GBM - 1) / GBM, 1, R), 128, GSMEM>>>(
        zptr, W1, (__half*)0, (const float*)0, (const float*)0, b1, W2,
        Nn, D, O, (size_t)Nn * D, 0, 0, 1);

    k_wreduce<<<R, 1024>>>();
    k_beta<<<1, 32>>>();
    k_out<<<(Nn * D / 4 + 255) / 256, 256>>>(out);
}

// round 10
// speedup vs baseline: 2.6774x; 1.0295x over previous
#include <cuda_runtime.h>
#include <cuda_fp16.h>
#include <stdint.h>
#include <math.h>

#define R  3
#define Nn 20000
#define E  320000
#define F  256
#define H  8
#define O  64
#define D  512
#define NCHUNK 20

// ---------------- scratch (static device globals; no allocations) ----------------
__device__ __half g_a16[(size_t)R * Nn * F];     // feats fp16
__device__ __half g_b16[(size_t)R * F * D];      // W fp16
__device__ __half g_w116[D * O];                 // W1 fp16
__device__ __half g_h16[(size_t)R * Nn * D];     // projected features fp16
__device__ __half g_z16[(size_t)R * Nn * D];     // GAT output fp16 (GEMM2 input)
__device__ float g_z[(size_t)R * Nn * D];        // GAT output fp32 (k_out input)
__device__ float g_el[R * Nn * H];
__device__ float g_er[R * Nn * H];
__device__ int   g_cnt[R * Nn];
__device__ int   g_rowptr[R * (Nn + 1)];
__device__ int   g_cursor[R * Nn];
__device__ int   g_bsum[R * NCHUNK];
__device__ int   g_boff[R * NCHUNK];
__device__ int   g_eid[(size_t)R * E];
__device__ float g_attn[(size_t)R * E * H];
__device__ float g_w[R * Nn];
__device__ float g_wmean[R];
__device__ float g_beta[R];

union H4 {
    float2 f2;
    __half2 h2[2];
};
__device__ __forceinline__ float2 f4_to_h4(float4 v) {
    H4 u;
    u.h2[0] = __floats2half2_rn(v.x, v.y);
    u.h2[1] = __floats2half2_rn(v.z, v.w);
    return u.f2;
}

// ---------------- zero scratch accumulators ----------------
__global__ void k_zero() {
    int t = blockIdx.x * blockDim.x + threadIdx.x;
    if (t < R * Nn) { g_cnt[t] = 0; g_w[t] = 0.f; }
    if (t < R * Nn * H) { g_el[t] = 0.f; g_er[t] = 0.f; }
}

// ---------------- fp32 -> fp16 pre-conversion (vectorized) ------------------------
#define NA4 (R * Nn * F / 4)
#define NB4 (R * F * D / 4)
#define NW4 (D * O / 4)
__global__ void k_cvt(const float* __restrict__ feats, const float* __restrict__ W,
                      const float* __restrict__ W1) {
    int i = blockIdx.x * blockDim.x + threadIdx.x;
    if (i < NA4)
        ((float2*)g_a16)[i] = f4_to_h4(((const float4*)feats)[i]);
    if (i < NB4)
        ((float2*)g_b16)[i] = f4_to_h4(((const float4*)W)[i]);
    if (i < NW4)
        ((float2*)g_w116)[i] = f4_to_h4(((const float4*)W1)[i]);
}

// ================= FP16 tensor-core GEMM (cp.async + ldmatrix + m16n8k16) ========
#define GBM 128
#define GBN 64
#define GBK 32
#define AST2 40
#define BST2 72
#define ASZ2 (GBM * AST2)
#define BSZ2 (GBK * BST2)
#define GSMEM (2 * (ASZ2 + BSZ2) * (int)sizeof(__half))

__device__ __forceinline__ void cpa16(unsigned dst, const void* src, int bytes) {
    asm volatile("cp.async.ca.shared.global [%0], [%1], 16, %2;\n"
                 :: "r"(dst), "l"(src), "r"(bytes));
}
__device__ __forceinline__ void cpa_commit() {
    asm volatile("cp.async.commit_group;\n");
}
__device__ __forceinline__ void cpa_wait0() {
    asm volatile("cp.async.wait_group 0;\n" ::: "memory");
}
__device__ __forceinline__ void ldsm4(unsigned* r, unsigned addr) {
    asm volatile("ldmatrix.sync.aligned.m8n8.x4.shared.b16 {%0,%1,%2,%3}, [%4];"
                 : "=r"(r[0]), "=r"(r[1]), "=r"(r[2]), "=r"(r[3]) : "r"(addr));
}
__device__ __forceinline__ void ldsm4t(unsigned* r, unsigned addr) {
    asm volatile("ldmatrix.sync.aligned.m8n8.x4.trans.shared.b16 {%0,%1,%2,%3}, [%4];"
                 : "=r"(r[0]), "=r"(r[1]), "=r"(r[2]), "=r"(r[3]) : "r"(addr));
}

__global__ void __launch_bounds__(128, 3) k_gemm_tc(
    const __half* __restrict__ A0, const __half* __restrict__ B0,
    __half* __restrict__ C16,
    const float* __restrict__ alp, const float* __restrict__ arp,
    const float* __restrict__ bias, const float* __restrict__ W2p,
    int M, int K, int Nd,
    size_t sA, size_t sB, size_t sC, int mode)
{
    extern __shared__ __half hsm[];
    __half* Asb0 = hsm;
    __half* Asb1 = hsm + ASZ2;
    __half* Bsb0 = hsm + 2 * ASZ2;
    __half* Bsb1 = hsm + 2 * ASZ2 + BSZ2;
    float* fsm = (float*)hsm;

    const int bz = blockIdx.z;
    const __half* A = A0 + (size_t)bz * sA;
    const __half* B = B0 + (size_t)bz * sB;

    const int tid  = threadIdx.x;
    const int lane = tid & 31, wid = tid >> 5;
    const int gid  = lane >> 2, tig = lane & 3;
    const int wm   = wid >> 1, wn = wid & 1;
    const int m0   = blockIdx.x * GBM, n0 = blockIdx.y * GBN;

    const unsigned uA0 = (unsigned)__cvta_generic_to_shared(Asb0);
    const unsigned uA1 = (unsigned)__cvta_generic_to_shared(Asb1);
    const unsigned uB0 = (unsigned)__cvta_generic_to_shared(Bsb0);
    const unsigned uB1 = (unsigned)__cvta_generic_to_shared(Bsb1);

    // cp.async chunk indices: A 4 chunks/thread, B 2 chunks/thread (16B each)
    int aRow[4], aCh[4], aByte[4], aOK[4];
#pragma unroll
    for (int j = 0; j < 4; j++) {
        int idx = tid + j * 128;           // 0..511
        aRow[j] = idx >> 2;                // 0..127
        aCh[j]  = (idx & 3) * 8;           // halves: 0,8,16,24
        int gr = m0 + aRow[j];
        aOK[j] = (gr < M) ? 16 : 0;
        aByte[j] = (aRow[j] * AST2 + aCh[j]) * 2;
    }
    int bRow[2], bCh[2], bByte[2];
#pragma unroll
    for (int j = 0; j < 2; j++) {
        int idx = tid + j * 128;           // 0..255
        bRow[j] = idx >> 3;                // 0..31
        bCh[j]  = (idx & 7) * 8;           // halves: 0..56
        bByte[j] = (bRow[j] * BST2 + bCh[j]) * 2;
    }

    const int aLRow = lane & 15, aLSel = lane >> 4;
    const int bLRow = lane & 15, bLSel = lane >> 4;

    float c[4][4][4];
#pragma unroll
    for (int i = 0; i < 4; i++)
#pragma unroll
        for (int j = 0; j < 4; j++) {
            c[i][j][0] = 0.f; c[i][j][1] = 0.f;
            c[i][j][2] = 0.f; c[i][j][3] = 0.f;
        }

    // prologue: stage tile 0 into buffer 0
#pragma unroll
    for (int j = 0; j < 4; j++) {
        int gr = m0 + aRow[j];
        int grc = (gr < M) ? gr : 0;
        cpa16(uA0 + aByte[j], A + (size_t)grc * K + aCh[j], aOK[j]);
    }
#pragma unroll
    for (int j = 0; j < 2; j++)
        cpa16(uB0 + bByte[j], B + (size_t)bRow[j] * Nd + n0 + bCh[j], 16);
    cpa_commit();
    cpa_wait0();
    __syncthreads();

    const int T = K / GBK;
    for (int it = 0; it < T; it++) {
        const int cur = it & 1;
        if (it + 1 < T) {
            const int k0n = (it + 1) * GBK;
            const unsigned uAn = cur ? uA0 : uA1;
            const unsigned uBn = cur ? uB0 : uB1;
#pragma unroll
            for (int j = 0; j < 4; j++) {
                int gr = m0 + aRow[j];
                int grc = (gr < M) ? gr : 0;
                cpa16(uAn + aByte[j], A + (size_t)grc * K + k0n + aCh[j], aOK[j]);
            }
#pragma unroll
            for (int j = 0; j < 2; j++)
                cpa16(uBn + bByte[j], B + (size_t)(k0n + bRow[j]) * Nd + n0 + bCh[j], 16);
            cpa_commit();
        }

        const unsigned uAc = cur ? uA1 : uA0;
        const unsigned uBc = cur ? uB1 : uB0;
#pragma unroll
        for (int kg = 0; kg < 2; kg++) {
            unsigned a[4][4], b[2][4];
#pragma unroll
            for (int mt = 0; mt < 4; mt++) {
                int row = wm * 64 + mt * 16 + aLRow;
                int ch  = kg * 16 + aLSel * 8;
                ldsm4(a[mt], uAc + (unsigned)(row * AST2 + ch) * 2u);
            }
#pragma unroll
            for (int nt2 = 0; nt2 < 2; nt2++) {
                int krow = kg * 16 + bLRow;
                int ncol = wn * 32 + nt2 * 16 + bLSel * 8;
                ldsm4t(b[nt2], uBc + (unsigned)(krow * BST2 + ncol) * 2u);
            }
#pragma unroll
            for (int mt = 0; mt < 4; mt++) {
#pragma unroll
                for (int nt = 0; nt < 4; nt++) {
                    unsigned bb0 = b[nt >> 1][(nt & 1) * 2];
                    unsigned bb1 = b[nt >> 1][(nt & 1) * 2 + 1];
                    asm volatile(
                        "mma.sync.aligned.m16n8k16.row.col.f32.f16.f16.f32 "
                        "{%0,%1,%2,%3}, {%4,%5,%6,%7}, {%8,%9}, {%0,%1,%2,%3};"
                        : "+f"(c[mt][nt][0]), "+f"(c[mt][nt][1]),
                          "+f"(c[mt][nt][2]), "+f"(c[mt][nt][3])
                        : "r"(a[mt][0]), "r"(a[mt][1]), "r"(a[mt][2]), "r"(a[mt][3]),
                          "r"(bb0), "r"(bb1));
                }
            }
        }

        if (it + 1 < T) cpa_wait0();
        __syncthreads();
    }

    // ---- epilogues ----
    if (mode == 0) {
        __half* C = C16 + (size_t)bz * sC;
        if (tid < 64) {
            fsm[tid]      = alp[bz * D + n0 + tid];
            fsm[64 + tid] = arp[bz * D + n0 + tid];
        }
        __syncthreads();
        const int hidx = blockIdx.y;
#pragma unroll
        for (int mt = 0; mt < 4; mt++) {
            int row = m0 + wm * 64 + mt * 16 + gid;
            float el0 = 0.f, er0 = 0.f, el1 = 0.f, er1 = 0.f;
#pragma unroll
            for (int nt = 0; nt < 4; nt++) {
                int o = wn * 32 + nt * 8 + 2 * tig;
                float al0 = fsm[o], al1 = fsm[o + 1];
                float ar0 = fsm[64 + o], ar1 = fsm[64 + o + 1];
                float v0 = c[mt][nt][0], v1 = c[mt][nt][1];
                float v2 = c[mt][nt][2], v3 = c[mt][nt][3];
                el0 = fmaf(v0, al0, fmaf(v1, al1, el0));
                er0 = fmaf(v0, ar0, fmaf(v1, ar1, er0));
                el1 = fmaf(v2, al0, fmaf(v3, al1, el1));
                er1 = fmaf(v2, ar0, fmaf(v3, ar1, er1));
                if (row < M)
                    *(__half2*)(C + (size_t)row * Nd + n0 + o) = __floats2half2_rn(v0, v1);
                if (row + 8 < M)
                    *(__half2*)(C + (size_t)(row + 8) * Nd + n0 + o) = __floats2half2_rn(v2, v3);
            }
#pragma unroll
            for (int off = 1; off <= 2; off <<= 1) {
                el0 += __shfl_xor_sync(0xFFFFFFFFu, el0, off);
                er0 += __shfl_xor_sync(0xFFFFFFFFu, er0, off);
                el1 += __shfl_xor_sync(0xFFFFFFFFu, el1, off);
                er1 += __shfl_xor_sync(0xFFFFFFFFu, er1, off);
            }
            if (tig == 0) {
                if (row < M) {
                    atomicAdd(&g_el[(bz * Nn + row) * H + hidx], el0);
                    atomicAdd(&g_er[(bz * Nn + row) * H + hidx], er0);
                }
                if (row + 8 < M) {
                    atomicAdd(&g_el[(bz * Nn + row + 8) * H + hidx], el1);
                    atomicAdd(&g_er[(bz * Nn + row + 8) * H + hidx], er1);
                }
            }
        }
    } else {
        if (tid < 64) {
            fsm[tid]      = bias[tid];
            fsm[64 + tid] = W2p[tid];
        }
        __syncthreads();
#pragma unroll
        for (int mt = 0; mt < 4; mt++) {
            int row = m0 + wm * 64 + mt * 16 + gid;
            float w0 = 0.f, w1 = 0.f;
#pragma unroll
            for (int nt = 0; nt < 4; nt++) {
                int o = wn * 32 + nt * 8 + 2 * tig;
                float b0 = fsm[o], b1v = fsm[o + 1];
                float w2a = fsm[64 + o], w2b = fsm[64 + o + 1];
                w0 = fmaf(tanhf(c[mt][nt][0] + b0), w2a,
                     fmaf(tanhf(c[mt][nt][1] + b1v), w2b, w0));
                w1 = fmaf(tanhf(c[mt][nt][2] + b0), w2a,
                     fmaf(tanhf(c[mt][nt][3] + b1v), w2b, w1));
            }
#pragma unroll
            for (int off = 1; off <= 2; off <<= 1) {
                w0 += __shfl_xor_sync(0xFFFFFFFFu, w0, off);
                w1 += __shfl_xor_sync(0xFFFFFFFFu, w1, off);
            }
            if (tig == 0) {
                if (row < M)     atomicAdd(&g_w[bz * Nn + row], w0);
                if (row + 8 < M) atomicAdd(&g_w[bz * Nn + row + 8], w1);
            }
        }
    }
}

// ---------------- CSR build -------------------------------------------------------
__global__ void k_hist(const int* __restrict__ dstA) {
    int t = blockIdx.x * blockDim.x + threadIdx.x;
    if (t >= R * E) return;
    int r = t / E;
    atomicAdd(&g_cnt[r * Nn + dstA[t]], 1);
}

__global__ void k_scan1() {
    int chunk = blockIdx.x, r = blockIdx.y;
    int t = threadIdx.x;
    __shared__ int ws[8];
    int base = chunk * 1024 + t * 4;
    const int* cnt = g_cnt + r * Nn;
    int v[4];
#pragma unroll
    for (int j = 0; j < 4; j++) {
        int i = base + j;
        v[j] = (i < Nn) ? cnt[i] : 0;
    }
    int s = v[0] + v[1] + v[2] + v[3];
    int lane = t & 31, w = t >> 5;
    int x = s;
#pragma unroll
    for (int off = 1; off < 32; off <<= 1) {
        int y = __shfl_up_sync(0xFFFFFFFFu, x, off);
        if (lane >= off) x += y;
    }
    if (lane == 31) ws[w] = x;
    __syncthreads();
    if (t < 8) {
        int y = ws[t];
#pragma unroll
        for (int off = 1; off < 8; off <<= 1) {
            int z = __shfl_up_sync(0xFFu, y, off);
            if (t >= off) y += z;
        }
        ws[t] = y;
    }
    __syncthreads();
    int excl = x - s + (w > 0 ? ws[w - 1] : 0);
    int* rp = g_rowptr + r * (Nn + 1);
    int run = excl;
#pragma unroll
    for (int j = 0; j < 4; j++) {
        int i = base + j;
        if (i < Nn) rp[i] = run;
        run += v[j];
    }
    if (t == 255) g_bsum[r * NCHUNK + chunk] = excl + s;
}

__global__ void k_scan2() {
    int r = threadIdx.x;
    if (r >= R) return;
    int acc = 0;
    for (int c = 0; c < NCHUNK; c++) {
        g_boff[r * NCHUNK + c] = acc;
        acc += g_bsum[r * NCHUNK + c];
    }
}

__global__ void k_scan3() {
    int chunk = blockIdx.x, r = blockIdx.y;
    int t = threadIdx.x;
    int off = g_boff[r * NCHUNK + chunk];
    int* rp = g_rowptr + r * (Nn + 1);
#pragma unroll
    for (int j = 0; j < 4; j++) {
        int i = chunk * 1024 + t * 4 + j;
        if (i < Nn) {
            int val = rp[i] + off;
            rp[i] = val;
            g_cursor[r * Nn + i] = val;
        }
    }
    if (chunk == 0 && t == 0) rp[Nn] = E;
}

__global__ void k_scatter(const int* __restrict__ dstA) {
    int t = blockIdx.x * blockDim.x + threadIdx.x;
    if (t >= R * E) return;
    int r = t / E, e = t % E;
    int d = dstA[t];
    int p = atomicAdd(&g_cursor[r * Nn + d], 1);
    g_eid[(size_t)r * E + p] = e;
}

// ---------------- edge softmax ----------------------------------------------------
__global__ void k_softmax(const int* __restrict__ srcA) {
    int t = blockIdx.x * blockDim.x + threadIdx.x;
    if (t >= R * Nn * H) return;
    int h = t % H;
    int n = (t / H) % Nn;
    int r = t / (H * Nn);
    int s0 = g_rowptr[r * (Nn + 1) + n];
    int s1 = g_rowptr[r * (Nn + 1) + n + 1];
    if (s1 == s0) return;
    float erv = g_er[t];
    const int* src = srcA + (size_t)r * E;
    const int* eid = g_eid + (size_t)r * E;
    float* attn = g_attn + (size_t)r * E * H;

    float m = -3.4e38f;
    for (int p = s0; p < s1; p++) {
        int e = eid[p];
        float s = g_el[(src[e] + r * Nn) * H + h] + erv;
        s = (s > 0.f) ? s : 0.2f * s;
        attn[(size_t)p * H + h] = s;
        m = fmaxf(m, s);
    }
    float den = 0.f;
    for (int p = s0; p < s1; p++) {
        float ex = expf(attn[(size_t)p * H + h] - m);
        attn[(size_t)p * H + h] = ex;
        den += ex;
    }
    float inv = 1.f / den;
    for (int p = s0; p < s1; p++)
        attn[(size_t)p * H + h] *= inv;
}

// ---------------- aggregate (writes z fp32 + z16 fp16) ----------------------------
__global__ void k_aggregate(const int* __restrict__ srcA, const float* __restrict__ bias) {
    int n = blockIdx.x;
    int r = blockIdx.y;
    int tid = threadIdx.x;
    int col = tid * 4;
    int h = tid >> 4;
    int s0 = g_rowptr[r * (Nn + 1) + n];
    int s1 = g_rowptr[r * (Nn + 1) + n + 1];
    const int* src = srcA + (size_t)r * E;
    const int* eid = g_eid + (size_t)r * E;
    const float* attn = g_attn + (size_t)r * E * H;
    const __half* hb = g_h16 + (size_t)r * Nn * D;

    float a0 = 0.f, a1 = 0.f, a2 = 0.f, a3 = 0.f;
    int p = s0;
    for (; p + 1 < s1; p += 2) {
        int e0 = eid[p], e1 = eid[p + 1];
        int sn0 = src[e0], sn1 = src[e1];
        float w0 = attn[(size_t)p * H + h];
        float w1 = attn[(size_t)(p + 1) * H + h];
        const __half2* q0 = (const __half2*)(hb + (size_t)sn0 * D + col);
        const __half2* q1 = (const __half2*)(hb + (size_t)sn1 * D + col);
        float2 u0 = __half22float2(q0[0]), u1 = __half22float2(q0[1]);
        float2 v0 = __half22float2(q1[0]), v1 = __half22float2(q1[1]);
        a0 = fmaf(w0, u0.x, a0); a1 = fmaf(w0, u0.y, a1);
        a2 = fmaf(w0, u1.x, a2); a3 = fmaf(w0, u1.y, a3);
        a0 = fmaf(w1, v0.x, a0); a1 = fmaf(w1, v0.y, a1);
        a2 = fmaf(w1, v1.x, a2); a3 = fmaf(w1, v1.y, a3);
    }
    if (p < s1) {
        int e = eid[p];
        int sn = src[e];
        float w = attn[(size_t)p * H + h];
        const __half2* q = (const __half2*)(hb + (size_t)sn * D + col);
        float2 u0 = __half22float2(q[0]), u1 = __half22float2(q[1]);
        a0 = fmaf(w, u0.x, a0); a1 = fmaf(w, u0.y, a1);
        a2 = fmaf(w, u1.x, a2); a3 = fmaf(w, u1.y, a3);
    }
    float4 bv = *(const float4*)(bias + r * D + col);
    float4 o;
    o.x = fminf(fmaxf(a0 + bv.x, 0.f), 6.f);
    o.y = fminf(fmaxf(a1 + bv.y, 0.f), 6.f);
    o.z = fminf(fmaxf(a2 + bv.z, 0.f), 6.f);
    o.w = fminf(fmaxf(a3 + bv.w, 0.f), 6.f);
    size_t base = ((size_t)(r * Nn + n)) * D + col;
    *(float4*)(g_z + base) = o;
    *(float2*)(g_z16 + base) = f4_to_h4(o);
}

// ---------------- deterministic mean over nodes -----------------------------------
__global__ void k_wreduce() {
    int r = blockIdx.x;
    __shared__ float sh[1024];
    float s = 0.f;
    for (int i = threadIdx.x; i < Nn; i += 1024) s += g_w[r * Nn + i];
    sh[threadIdx.x] = s;
    __syncthreads();
    for (int off = 512; off > 0; off >>= 1) {
        if (threadIdx.x < off) sh[threadIdx.x] += sh[threadIdx.x + off];
        __syncthreads();
    }
    if (threadIdx.x == 0) g_wmean[r] = sh[0] / (float)Nn;
}

__global__ void k_beta() {
    if (threadIdx.x == 0) {
        float m = fmaxf(g_wmean[0], fmaxf(g_wmean[1], g_wmean[2]));
        float e0 = expf(g_wmean[0] - m);
        float e1 = expf(g_wmean[1] - m);
        float e2 = expf(g_wmean[2] - m);
        float inv = 1.f / (e0 + e1 + e2);
        g_beta[0] = e0 * inv;
        g_beta[1] = e1 * inv;
        g_beta[2] = e2 * inv;
    }
}

// ---------------- out = sum_r beta[r] * z[:, r, :] --------------------------------
__global__ void k_out(float* __restrict__ out) {
    int i = blockIdx.x * blockDim.x + threadIdx.x;
    if (i >= Nn * D / 4) return;
    float b0 = g_beta[0], b1 = g_beta[1], b2 = g_beta[2];
    const float4* z0 = (const float4*)g_z;
    const float4* z1 = (const float4*)(g_z + (size_t)Nn * D);
    const float4* z2 = (const float4*)(g_z + (size_t)2 * Nn * D);
    float4 v0 = z0[i], v1 = z1[i], v2 = z2[i];
    float4 o;
    o.x = b0 * v0.x + b1 * v1.x + b2 * v2.x;
    o.y = b0 * v0.y + b1 * v1.y + b2 * v2.y;
    o.z = b0 * v0.z + b1 * v1.z + b2 * v2.z;
    o.w = b0 * v0.w + b1 * v1.w + b2 * v2.w;
    ((float4*)out)[i] = o;
}

// ---------------- host ------------------------------------------------------------
extern "C" void kernel_launch(void* const* d_in, const int* in_sizes, int n_in,
                              void* d_out, int out_size) {
    const float* feats = (const float*)d_in[0];
    const int*   src   = (const int*)d_in[1];
    const int*   dst   = (const int*)d_in[2];
    const float* W     = (const float*)d_in[3];
    const float* al    = (const float*)d_in[4];
    const float* ar    = (const float*)d_in[5];
    const float* bias  = (const float*)d_in[6];
    const float* W1    = (const float*)d_in[7];
    const float* b1    = (const float*)d_in[8];
    const float* W2    = (const float*)d_in[9];
    float* out = (float*)d_out;

    __half *aptr, *bptr, *w1ptr, *hptr, *z16ptr;
    cudaGetSymbolAddress((void**)&aptr, g_a16);
    cudaGetSymbolAddress((void**)&bptr, g_b16);
    cudaGetSymbolAddress((void**)&w1ptr, g_w116);
    cudaGetSymbolAddress((void**)&hptr, g_h16);
    cudaGetSymbolAddress((void**)&z16ptr, g_z16);

    cudaFuncSetAttribute(k_gemm_tc, cudaFuncAttributeMaxDynamicSharedMemorySize,
                         GSMEM);

    k_zero<<<(R * Nn * H + 255) / 256, 256>>>();
    k_cvt<<<(NA4 + 255) / 256, 256>>>(feats, W, W1);

    // GEMM1: h = a16 @ b16 (fp16 in/out) + fused el/er
    k_gemm_tc<<<dim3((Nn + GBM - 1) / GBM, D / GBN, R), 128, GSMEM>>>(
        aptr, bptr, hptr, al, ar, (const float*)0, (const float*)0,
        Nn, F, D, (size_t)Nn * F, (size_t)F * D, (size_t)Nn * D, 0);

    k_hist<<<(R * E + 255) / 256, 256>>>(dst);
    k_scan1<<<dim3(NCHUNK, R), 256>>>();
    k_scan2<<<1, 32>>>();
    k_scan3<<<dim3(NCHUNK, R), 256>>>();
    k_scatter<<<(R * E + 255) / 256, 256>>>(dst);

    k_softmax<<<(R * Nn * H + 255) / 256, 256>>>(src);
    k_aggregate<<<dim3(Nn, R), 128>>>(src, bias);

    // GEMM2: w += tanh(z16 @ w116 + b1) @ W2
    k_gemm_tc<<<dim3((Nn + GBM - 1) / GBM, 1, R), 128, GSMEM>>>(
        z16ptr, w1ptr, (__half*)0, (const float*)0, (const float*)0, b1, W2,
        Nn, D, O, (size_t)Nn * D, 0, 0, 1);

    k_wreduce<<<R, 1024>>>();
    k_beta<<<1, 32>>>();
    k_out<<<(Nn * D / 4 + 255) / 256, 256>>>(out);
}

// round 11
// speedup vs baseline: 2.7280x; 1.0189x over previous
#include <cuda_runtime.h>
#include <cuda_fp16.h>
#include <stdint.h>
#include <math.h>

#define R  3
#define Nn 20000
#define E  320000
#define F  256
#define H  8
#define O  64
#define D  512
#define NCHUNK 20
#define CAP 96

// ---------------- scratch (static device globals; no allocations) ----------------
__device__ __half g_a16[(size_t)R * Nn * F];
__device__ __half g_b16[(size_t)R * F * D];
__device__ __half g_w116[D * O];
__device__ __half g_h16[(size_t)R * Nn * D];
__device__ __half g_z16[(size_t)R * Nn * D];
__device__ float g_z[(size_t)R * Nn * D];
__device__ float g_el[R * Nn * H];
__device__ float g_er[R * Nn * H];
__device__ int   g_cnt[R * Nn];
__device__ int   g_rowptr[R * (Nn + 1)];
__device__ int   g_cursor[R * Nn];
__device__ int   g_bsum[R * NCHUNK];
__device__ int   g_boff[R * NCHUNK];
__device__ int   g_eid[(size_t)R * E];
__device__ float g_attn[(size_t)R * E * H];     // fallback buffer for deg > CAP
__device__ float g_w[R * Nn];
__device__ float g_wmean[R];

union H4 {
    float2 f2;
    __half2 h2[2];
};
__device__ __forceinline__ float2 f4_to_h4(float4 v) {
    H4 u;
    u.h2[0] = __floats2half2_rn(v.x, v.y);
    u.h2[1] = __floats2half2_rn(v.z, v.w);
    return u.f2;
}

// ---------------- init: zero accumulators + fp32->fp16 conversion -----------------
#define NA4 (R * Nn * F / 4)
#define NB4 (R * F * D / 4)
#define NW4 (D * O / 4)
__global__ void k_init(const float* __restrict__ feats, const float* __restrict__ W,
                       const float* __restrict__ W1) {
    int i = blockIdx.x * blockDim.x + threadIdx.x;
    if (i < NA4)
        ((float2*)g_a16)[i] = f4_to_h4(((const float4*)feats)[i]);
    if (i < NB4)
        ((float2*)g_b16)[i] = f4_to_h4(((const float4*)W)[i]);
    if (i < NW4)
        ((float2*)g_w116)[i] = f4_to_h4(((const float4*)W1)[i]);
    if (i < R * Nn) { g_cnt[i] = 0; g_w[i] = 0.f; }
    if (i < R * Nn * H) { g_el[i] = 0.f; g_er[i] = 0.f; }
}

// ================= FP16 tensor-core GEMM (cp.async + ldmatrix + m16n8k16) ========
// mode 0 also hosts histogram blocks at blockIdx.y == D/GBN (overlapped with GEMM).
#define GBM 128
#define GBN 64
#define GBK 32
#define AST2 40
#define BST2 72
#define ASZ2 (GBM * AST2)
#define BSZ2 (GBK * BST2)
#define GSMEM (2 * (ASZ2 + BSZ2) * (int)sizeof(__half))

__device__ __forceinline__ void cpa16(unsigned dst, const void* src, int bytes) {
    asm volatile("cp.async.ca.shared.global [%0], [%1], 16, %2;\n"
                 :: "r"(dst), "l"(src), "r"(bytes));
}
__device__ __forceinline__ void cpa_commit() {
    asm volatile("cp.async.commit_group;\n");
}
__device__ __forceinline__ void cpa_wait0() {
    asm volatile("cp.async.wait_group 0;\n" ::: "memory");
}
__device__ __forceinline__ void ldsm4(unsigned* r, unsigned addr) {
    asm volatile("ldmatrix.sync.aligned.m8n8.x4.shared.b16 {%0,%1,%2,%3}, [%4];"
                 : "=r"(r[0]), "=r"(r[1]), "=r"(r[2]), "=r"(r[3]) : "r"(addr));
}
__device__ __forceinline__ void ldsm4t(unsigned* r, unsigned addr) {
    asm volatile("ldmatrix.sync.aligned.m8n8.x4.trans.shared.b16 {%0,%1,%2,%3}, [%4];"
                 : "=r"(r[0]), "=r"(r[1]), "=r"(r[2]), "=r"(r[3]) : "r"(addr));
}

__global__ void __launch_bounds__(128, 3) k_gemm_tc(
    const __half* __restrict__ A0, const __half* __restrict__ B0,
    __half* __restrict__ C16,
    const float* __restrict__ alp, const float* __restrict__ arp,
    const float* __restrict__ bias, const float* __restrict__ W2p,
    const int* __restrict__ dstA,
    int M, int K, int Nd,
    size_t sA, size_t sB, size_t sC, int mode)
{
    const int bz = blockIdx.z;
    const int tid = threadIdx.x;

    // ---- histogram blocks (mode 0 only, overlapped with GEMM wave) ----
    if (mode == 0 && blockIdx.y == (unsigned)(D / GBN)) {
        int base = blockIdx.x * 2048;
#pragma unroll
        for (int j = 0; j < 16; j++) {
            int e = base + j * 128 + tid;
            if (e < E) atomicAdd(&g_cnt[bz * Nn + dstA[(size_t)bz * E + e]], 1);
        }
        return;
    }

    extern __shared__ __half hsm[];
    __half* Asb0 = hsm;
    __half* Asb1 = hsm + ASZ2;
    __half* Bsb0 = hsm + 2 * ASZ2;
    __half* Bsb1 = hsm + 2 * ASZ2 + BSZ2;
    float* fsm = (float*)hsm;

    const __half* A = A0 + (size_t)bz * sA;
    const __half* B = B0 + (size_t)bz * sB;

    const int lane = tid & 31, wid = tid >> 5;
    const int gid  = lane >> 2, tig = lane & 3;
    const int wm   = wid >> 1, wn = wid & 1;
    const int m0   = blockIdx.x * GBM, n0 = blockIdx.y * GBN;

    const unsigned uA0 = (unsigned)__cvta_generic_to_shared(Asb0);
    const unsigned uA1 = (unsigned)__cvta_generic_to_shared(Asb1);
    const unsigned uB0 = (unsigned)__cvta_generic_to_shared(Bsb0);
    const unsigned uB1 = (unsigned)__cvta_generic_to_shared(Bsb1);

    int aRow[4], aCh[4], aByte[4], aOK[4];
#pragma unroll
    for (int j = 0; j < 4; j++) {
        int idx = tid + j * 128;
        aRow[j] = idx >> 2;
        aCh[j]  = (idx & 3) * 8;
        int gr = m0 + aRow[j];
        aOK[j] = (gr < M) ? 16 : 0;
        aByte[j] = (aRow[j] * AST2 + aCh[j]) * 2;
    }
    int bRow[2], bCh[2], bByte[2];
#pragma unroll
    for (int j = 0; j < 2; j++) {
        int idx = tid + j * 128;
        bRow[j] = idx >> 3;
        bCh[j]  = (idx & 7) * 8;
        bByte[j] = (bRow[j] * BST2 + bCh[j]) * 2;
    }

    const int aLRow = lane & 15, aLSel = lane >> 4;
    const int bLRow = lane & 15, bLSel = lane >> 4;

    float c[4][4][4];
#pragma unroll
    for (int i = 0; i < 4; i++)
#pragma unroll
        for (int j = 0; j < 4; j++) {
            c[i][j][0] = 0.f; c[i][j][1] = 0.f;
            c[i][j][2] = 0.f; c[i][j][3] = 0.f;
        }

#pragma unroll
    for (int j = 0; j < 4; j++) {
        int gr = m0 + aRow[j];
        int grc = (gr < M) ? gr : 0;
        cpa16(uA0 + aByte[j], A + (size_t)grc * K + aCh[j], aOK[j]);
    }
#pragma unroll
    for (int j = 0; j < 2; j++)
        cpa16(uB0 + bByte[j], B + (size_t)bRow[j] * Nd + n0 + bCh[j], 16);
    cpa_commit();
    cpa_wait0();
    __syncthreads();

    const int T = K / GBK;
    for (int it = 0; it < T; it++) {
        const int cur = it & 1;
        if (it + 1 < T) {
            const int k0n = (it + 1) * GBK;
            const unsigned uAn = cur ? uA0 : uA1;
            const unsigned uBn = cur ? uB0 : uB1;
#pragma unroll
            for (int j = 0; j < 4; j++) {
                int gr = m0 + aRow[j];
                int grc = (gr < M) ? gr : 0;
                cpa16(uAn + aByte[j], A + (size_t)grc * K + k0n + aCh[j], aOK[j]);
            }
#pragma unroll
            for (int j = 0; j < 2; j++)
                cpa16(uBn + bByte[j], B + (size_t)(k0n + bRow[j]) * Nd + n0 + bCh[j], 16);
            cpa_commit();
        }

        const unsigned uAc = cur ? uA1 : uA0;
        const unsigned uBc = cur ? uB1 : uB0;
#pragma unroll
        for (int kg = 0; kg < 2; kg++) {
            unsigned a[4][4], b[2][4];
#pragma unroll
            for (int mt = 0; mt < 4; mt++) {
                int row = wm * 64 + mt * 16 + aLRow;
                int ch  = kg * 16 + aLSel * 8;
                ldsm4(a[mt], uAc + (unsigned)(row * AST2 + ch) * 2u);
            }
#pragma unroll
            for (int nt2 = 0; nt2 < 2; nt2++) {
                int krow = kg * 16 + bLRow;
                int ncol = wn * 32 + nt2 * 16 + bLSel * 8;
                ldsm4t(b[nt2], uBc + (unsigned)(krow * BST2 + ncol) * 2u);
            }
#pragma unroll
            for (int mt = 0; mt < 4; mt++) {
#pragma unroll
                for (int nt = 0; nt < 4; nt++) {
                    unsigned bb0 = b[nt >> 1][(nt & 1) * 2];
                    unsigned bb1 = b[nt >> 1][(nt & 1) * 2 + 1];
                    asm volatile(
                        "mma.sync.aligned.m16n8k16.row.col.f32.f16.f16.f32 "
                        "{%0,%1,%2,%3}, {%4,%5,%6,%7}, {%8,%9}, {%0,%1,%2,%3};"
                        : "+f"(c[mt][nt][0]), "+f"(c[mt][nt][1]),
                          "+f"(c[mt][nt][2]), "+f"(c[mt][nt][3])
                        : "r"(a[mt][0]), "r"(a[mt][1]), "r"(a[mt][2]), "r"(a[mt][3]),
                          "r"(bb0), "r"(bb1));
                }
            }
        }

        if (it + 1 < T) cpa_wait0();
        __syncthreads();
    }

    // ---- epilogues ----
    if (mode == 0) {
        __half* C = C16 + (size_t)bz * sC;
        if (tid < 64) {
            fsm[tid]      = alp[bz * D + n0 + tid];
            fsm[64 + tid] = arp[bz * D + n0 + tid];
        }
        __syncthreads();
        const int hidx = blockIdx.y;
#pragma unroll
        for (int mt = 0; mt < 4; mt++) {
            int row = m0 + wm * 64 + mt * 16 + gid;
            float el0 = 0.f, er0 = 0.f, el1 = 0.f, er1 = 0.f;
#pragma unroll
            for (int nt = 0; nt < 4; nt++) {
                int o = wn * 32 + nt * 8 + 2 * tig;
                float al0 = fsm[o], al1 = fsm[o + 1];
                float ar0 = fsm[64 + o], ar1 = fsm[64 + o + 1];
                float v0 = c[mt][nt][0], v1 = c[mt][nt][1];
                float v2 = c[mt][nt][2], v3 = c[mt][nt][3];
                el0 = fmaf(v0, al0, fmaf(v1, al1, el0));
                er0 = fmaf(v0, ar0, fmaf(v1, ar1, er0));
                el1 = fmaf(v2, al0, fmaf(v3, al1, el1));
                er1 = fmaf(v2, ar0, fmaf(v3, ar1, er1));
                if (row < M)
                    *(__half2*)(C + (size_t)row * Nd + n0 + o) = __floats2half2_rn(v0, v1);
                if (row + 8 < M)
                    *(__half2*)(C + (size_t)(row + 8) * Nd + n0 + o) = __floats2half2_rn(v2, v3);
            }
#pragma unroll
            for (int off = 1; off <= 2; off <<= 1) {
                el0 += __shfl_xor_sync(0xFFFFFFFFu, el0, off);
                er0 += __shfl_xor_sync(0xFFFFFFFFu, er0, off);
                el1 += __shfl_xor_sync(0xFFFFFFFFu, el1, off);
                er1 += __shfl_xor_sync(0xFFFFFFFFu, er1, off);
            }
            if (tig == 0) {
                if (row < M) {
                    atomicAdd(&g_el[(bz * Nn + row) * H + hidx], el0);
                    atomicAdd(&g_er[(bz * Nn + row) * H + hidx], er0);
                }
                if (row + 8 < M) {
                    atomicAdd(&g_el[(bz * Nn + row + 8) * H + hidx], el1);
                    atomicAdd(&g_er[(bz * Nn + row + 8) * H + hidx], er1);
                }
            }
        }
    } else {
        if (tid < 64) {
            fsm[tid]      = bias[tid];
            fsm[64 + tid] = W2p[tid];
        }
        __syncthreads();
#pragma unroll
        for (int mt = 0; mt < 4; mt++) {
            int row = m0 + wm * 64 + mt * 16 + gid;
            float w0 = 0.f, w1 = 0.f;
#pragma unroll
            for (int nt = 0; nt < 4; nt++) {
                int o = wn * 32 + nt * 8 + 2 * tig;
                float b0 = fsm[o], b1v = fsm[o + 1];
                float w2a = fsm[64 + o], w2b = fsm[64 + o + 1];
                w0 = fmaf(tanhf(c[mt][nt][0] + b0), w2a,
                     fmaf(tanhf(c[mt][nt][1] + b1v), w2b, w0));
                w1 = fmaf(tanhf(c[mt][nt][2] + b0), w2a,
                     fmaf(tanhf(c[mt][nt][3] + b1v), w2b, w1));
            }
#pragma unroll
            for (int off = 1; off <= 2; off <<= 1) {
                w0 += __shfl_xor_sync(0xFFFFFFFFu, w0, off);
                w1 += __shfl_xor_sync(0xFFFFFFFFu, w1, off);
            }
            if (tig == 0) {
                if (row < M)     atomicAdd(&g_w[bz * Nn + row], w0);
                if (row + 8 < M) atomicAdd(&g_w[bz * Nn + row + 8], w1);
            }
        }
    }
}

// ---------------- CSR scan + scatter ----------------------------------------------
__global__ void k_scan1() {
    int chunk = blockIdx.x, r = blockIdx.y;
    int t = threadIdx.x;
    __shared__ int ws[8];
    int base = chunk * 1024 + t * 4;
    const int* cnt = g_cnt + r * Nn;
    int v[4];
#pragma unroll
    for (int j = 0; j < 4; j++) {
        int i = base + j;
        v[j] = (i < Nn) ? cnt[i] : 0;
    }
    int s = v[0] + v[1] + v[2] + v[3];
    int lane = t & 31, w = t >> 5;
    int x = s;
#pragma unroll
    for (int off = 1; off < 32; off <<= 1) {
        int y = __shfl_up_sync(0xFFFFFFFFu, x, off);
        if (lane >= off) x += y;
    }
    if (lane == 31) ws[w] = x;
    __syncthreads();
    if (t < 8) {
        int y = ws[t];
#pragma unroll
        for (int off = 1; off < 8; off <<= 1) {
            int z = __shfl_up_sync(0xFFu, y, off);
            if (t >= off) y += z;
        }
        ws[t] = y;
    }
    __syncthreads();
    int excl = x - s + (w > 0 ? ws[w - 1] : 0);
    int* rp = g_rowptr + r * (Nn + 1);
    int run = excl;
#pragma unroll
    for (int j = 0; j < 4; j++) {
        int i = base + j;
        if (i < Nn) rp[i] = run;
        run += v[j];
    }
    if (t == 255) g_bsum[r * NCHUNK + chunk] = excl + s;
}

__global__ void k_scan2() {
    int r = threadIdx.x;
    if (r >= R) return;
    int acc = 0;
    for (int c = 0; c < NCHUNK; c++) {
        g_boff[r * NCHUNK + c] = acc;
        acc += g_bsum[r * NCHUNK + c];
    }
}

__global__ void k_scan3() {
    int chunk = blockIdx.x, r = blockIdx.y;
    int t = threadIdx.x;
    int off = g_boff[r * NCHUNK + chunk];
    int* rp = g_rowptr + r * (Nn + 1);
#pragma unroll
    for (int j = 0; j < 4; j++) {
        int i = chunk * 1024 + t * 4 + j;
        if (i < Nn) {
            int val = rp[i] + off;
            rp[i] = val;
            g_cursor[r * Nn + i] = val;
        }
    }
    if (chunk == 0 && t == 0) rp[Nn] = E;
}

__global__ void k_scatter(const int* __restrict__ dstA) {
    int t = blockIdx.x * blockDim.x + threadIdx.x;
    if (t >= R * E) return;
    int r = t / E, e = t % E;
    int d = dstA[t];
    int p = atomicAdd(&g_cursor[r * Nn + d], 1);
    g_eid[(size_t)r * E + p] = e;
}

// ---------------- fused edge-softmax + aggregate ----------------------------------
// one 128-thread block per (dst, r); online softmax in smem, then gather-aggregate
__global__ void __launch_bounds__(128) k_sagg(const int* __restrict__ srcA,
                                              const float* __restrict__ bias) {
    int n = blockIdx.x, r = blockIdx.y;
    int tid = threadIdx.x;
    int s0 = g_rowptr[r * (Nn + 1) + n];
    int s1 = g_rowptr[r * (Nn + 1) + n + 1];
    int deg = s1 - s0;

    __shared__ float s_attn[CAP * 8];
    __shared__ float s_m[4][8], s_s[4][8];
    __shared__ float s_M[8], s_I[8];

    const int* eid = g_eid + (size_t)r * E;
    const int* src = srcA + (size_t)r * E;
    const float* elb = g_el + (size_t)r * Nn * H;
    float* buf = (deg <= CAP) ? s_attn : (g_attn + ((size_t)r * E + s0) * H);

    // phase 1: scores + per-thread online softmax (thread = (edge lane, head))
    int h = tid & 7, li0 = tid >> 3;     // 16 edge lanes x 8 heads
    float erv = g_er[((size_t)r * Nn + n) * H + h];
    float m = -3.4e38f, ssum = 0.f;
    for (int li = li0; li < deg; li += 16) {
        int e = eid[s0 + li];
        float v = elb[(size_t)src[e] * H + h] + erv;
        v = (v > 0.f) ? v : 0.2f * v;
        buf[li * 8 + h] = v;
        if (v > m) {
            ssum = ssum * expf(m - v) + 1.f;
            m = v;
        } else {
            ssum += expf(v - m);
        }
    }
    // combine 16 lanes per head: within warp (lanes h, h+8, h+16, h+24), then across warps
    int lane = tid & 31, w = tid >> 5;
#pragma unroll
    for (int off = 8; off <= 16; off <<= 1) {
        float m2 = __shfl_xor_sync(0xFFFFFFFFu, m, off);
        float s2 = __shfl_xor_sync(0xFFFFFFFFu, ssum, off);
        float M = fmaxf(m, m2);
        ssum = ssum * expf(m - M) + s2 * expf(m2 - M);
        m = M;
    }
    if (lane < 8) { s_m[w][lane] = m; s_s[w][lane] = ssum; }
    __syncthreads();
    if (tid < 8) {
        float M = s_m[0][tid], S = s_s[0][tid];
#pragma unroll
        for (int ww = 1; ww < 4; ww++) {
            float m2 = s_m[ww][tid], s2 = s_s[ww][tid];
            float Mx = fmaxf(M, m2);
            S = S * expf(M - Mx) + s2 * expf(m2 - Mx);
            M = Mx;
        }
        s_M[tid] = M;
        s_I[tid] = 1.f / S;
    }
    __syncthreads();

    // phase 2: normalize weights in buf
    for (int idx = tid; idx < deg * 8; idx += 128)
        buf[idx] = expf(buf[idx] - s_M[idx & 7]) * s_I[idx & 7];
    __syncthreads();

    // phase 3: aggregate h rows
    int col = tid * 4, hh = tid >> 4;
    const __half* hb = g_h16 + (size_t)r * Nn * D;
    float a0 = 0.f, a1 = 0.f, a2 = 0.f, a3 = 0.f;
    int li = 0;
    for (; li + 1 < deg; li += 2) {
        int e0 = eid[s0 + li], e1 = eid[s0 + li + 1];
        int sn0 = src[e0], sn1 = src[e1];
        float w0 = buf[li * 8 + hh];
        float w1 = buf[(li + 1) * 8 + hh];
        const __half2* q0 = (const __half2*)(hb + (size_t)sn0 * D + col);
        const __half2* q1 = (const __half2*)(hb + (size_t)sn1 * D + col);
        float2 u0 = __half22float2(q0[0]), u1 = __half22float2(q0[1]);
        float2 v0 = __half22float2(q1[0]), v1 = __half22float2(q1[1]);
        a0 = fmaf(w0, u0.x, a0); a1 = fmaf(w0, u0.y, a1);
        a2 = fmaf(w0, u1.x, a2); a3 = fmaf(w0, u1.y, a3);
        a0 = fmaf(w1, v0.x, a0); a1 = fmaf(w1, v0.y, a1);
        a2 = fmaf(w1, v1.x, a2); a3 = fmaf(w1, v1.y, a3);
    }
    if (li < deg) {
        int e = eid[s0 + li];
        int sn = src[e];
        float wv = buf[li * 8 + hh];
        const __half2* q = (const __half2*)(hb + (size_t)sn * D + col);
        float2 u0 = __half22float2(q[0]), u1 = __half22float2(q[1]);
        a0 = fmaf(wv, u0.x, a0); a1 = fmaf(wv, u0.y, a1);
        a2 = fmaf(wv, u1.x, a2); a3 = fmaf(wv, u1.y, a3);
    }
    float4 bv = *(const float4*)(bias + r * D + col);
    float4 o;
    o.x = fminf(fmaxf(a0 + bv.x, 0.f), 6.f);
    o.y = fminf(fmaxf(a1 + bv.y, 0.f), 6.f);
    o.z = fminf(fmaxf(a2 + bv.z, 0.f), 6.f);
    o.w = fminf(fmaxf(a3 + bv.w, 0.f), 6.f);
    size_t base = ((size_t)(r * Nn + n)) * D + col;
    *(float4*)(g_z + base) = o;
    *(float2*)(g_z16 + base) = f4_to_h4(o);
}

// ---------------- deterministic mean over nodes -----------------------------------
__global__ void k_wreduce() {
    int r = blockIdx.x;
    __shared__ float sh[1024];
    float s = 0.f;
    for (int i = threadIdx.x; i < Nn; i += 1024) s += g_w[r * Nn + i];
    sh[threadIdx.x] = s;
    __syncthreads();
    for (int off = 512; off > 0; off >>= 1) {
        if (threadIdx.x < off) sh[threadIdx.x] += sh[threadIdx.x + off];
        __syncthreads();
    }
    if (threadIdx.x == 0) g_wmean[r] = sh[0] / (float)Nn;
}

// ---------------- out = sum_r beta[r] * z[:, r, :] (beta inline) ------------------
__global__ void k_out(float* __restrict__ out) {
    int i = blockIdx.x * blockDim.x + threadIdx.x;
    if (i >= Nn * D / 4) return;
    float w0 = g_wmean[0], w1 = g_wmean[1], w2 = g_wmean[2];
    float mx = fmaxf(w0, fmaxf(w1, w2));
    float e0 = expf(w0 - mx), e1 = expf(w1 - mx), e2 = expf(w2 - mx);
    float inv = 1.f / (e0 + e1 + e2);
    float b0 = e0 * inv, b1 = e1 * inv, b2 = e2 * inv;
    const float4* z0 = (const float4*)g_z;
    const float4* z1 = (const float4*)(g_z + (size_t)Nn * D);
    const float4* z2 = (const float4*)(g_z + (size_t)2 * Nn * D);
    float4 v0 = z0[i], v1 = z1[i], v2 = z2[i];
    float4 o;
    o.x = b0 * v0.x + b1 * v1.x + b2 * v2.x;
    o.y = b0 * v0.y + b1 * v1.y + b2 * v2.y;
    o.z = b0 * v0.z + b1 * v1.z + b2 * v2.z;
    o.w = b0 * v0.w + b1 * v1.w + b2 * v2.w;
    ((float4*)out)[i] = o;
}

// ---------------- host ------------------------------------------------------------
extern "C" void kernel_launch(void* const* d_in, const int* in_sizes, int n_in,
                              void* d_out, int out_size) {
    const float* feats = (const float*)d_in[0];
    const int*   src   = (const int*)d_in[1];
    const int*   dst   = (const int*)d_in[2];
    const float* W     = (const float*)d_in[3];
    const float* al    = (const float*)d_in[4];
    const float* ar    = (const float*)d_in[5];
    const float* bias  = (const float*)d_in[6];
    const float* W1    = (const float*)d_in[7];
    const float* b1    = (const float*)d_in[8];
    const float* W2    = (const float*)d_in[9];
    float* out = (float*)d_out;

    __half *aptr, *bptr, *w1ptr, *hptr, *z16ptr;
    cudaGetSymbolAddress((void**)&aptr, g_a16);
    cudaGetSymbolAddress((void**)&bptr, g_b16);
    cudaGetSymbolAddress((void**)&w1ptr, g_w116);
    cudaGetSymbolAddress((void**)&hptr, g_h16);
    cudaGetSymbolAddress((void**)&z16ptr, g_z16);

    cudaFuncSetAttribute(k_gemm_tc, cudaFuncAttributeMaxDynamicSharedMemorySize,
                         GSMEM);

    k_init<<<(NA4 + 255) / 256, 256>>>(feats, W, W1);

    // GEMM1 + overlapped histogram (blockIdx.y == 8)
    k_gemm_tc<<<dim3((Nn + GBM - 1) / GBM, D / GBN + 1, R), 128, GSMEM>>>(
        aptr, bptr, hptr, al, ar, (const float*)0, (const float*)0, dst,
        Nn, F, D, (size_t)Nn * F, (size_t)F * D, (size_t)Nn * D, 0);

    k_scan1<<<dim3(NCHUNK, R), 256>>>();
    k_scan2<<<1, 32>>>();
    k_scan3<<<dim3(NCHUNK, R), 256>>>();
    k_scatter<<<(R * E + 255) / 256, 256>>>(dst);

    // fused edge softmax + aggregation
    k_sagg<<<dim3(Nn, R), 128>>>(src, bias);

    // GEMM2: w += tanh(z16 @ w116 + b1) @ W2
    k_gemm_tc<<<dim3((Nn + GBM - 1) / GBM, 1, R), 128, GSMEM>>>(
        z16ptr, w1ptr, (__half*)0, (const float*)0, (const float*)0, b1, W2,
        (const int*)0, Nn, D, O, (size_t)Nn * D, 0, 0, 1);

    k_wreduce<<<R, 1024>>>();
    k_out<<<(Nn * D / 4 + 255) / 256, 256>>>(out);
}